// round 11
// baseline (speedup 1.0000x reference)
#include <cuda_runtime.h>
#include <cuda_fp16.h>
#include <cstdint>
#include <math.h>

#define NB 64
#define TT 512
#define EE 512
#define KK 512
#define VV 512
#define BKH 64                  // K halves per chunk (qkt/av)
#define SA  72                  // A / NT-B smem row stride (64 + 8 pad)
#define SBT 136                 // trans-B smem row stride (128 + 8 pad)

#define AHALVES (128 * SA)                  // 9216 halves
#define BHALVES (128 * SA)
#define STAGEH  (AHALVES + BHALVES)         // 18432 halves = 36864 B
#define SMEM_BYTES (2 * STAGEH * 2)         // 73728 B (qkt/av)

// proj A-stationary config
#define SAW 520                              // resident A stride (512 + 8)
#define PA_HALVES (64 * SAW)                 // 33280
#define PB_HALVES (64 * SBT)                 // 8704 per buffer
#define PROJ_SMEM ((PA_HALVES + 2 * PB_HALVES) * 2)   // 101376 B

// ---------------------------------------------------------------------------
// Device scratch
// ---------------------------------------------------------------------------
__device__ __half g_xh[(size_t)NB * TT * EE];
__device__ __half g_Wh[(size_t)3 * EE * KK];    // W natural [e][k] fp16
__device__ __half g_Qh[(size_t)NB * TT * KK];
__device__ __half g_Kh[(size_t)NB * TT * KK];
__device__ __half g_Vh[(size_t)NB * TT * VV];   // V natural [t][v] fp16
__device__ float  g_S [(size_t)NB * TT * TT];
__device__ __half g_Sh[(size_t)NB * TT * TT];

// ---------------------------------------------------------------------------
// Helpers
// ---------------------------------------------------------------------------
__device__ __forceinline__ uint32_t smem_u32(const void* p) {
    uint32_t a;
    asm("{ .reg .u64 t; cvta.to.shared.u64 t, %1; cvt.u32.u64 %0, t; }"
        : "=r"(a) : "l"(p));
    return a;
}

#define CP_ASYNC16(dst, src) \
    asm volatile("cp.async.cg.shared.global [%0], [%1], 16;" \
                 :: "r"(dst), "l"(src) : "memory")
#define CP_COMMIT() asm volatile("cp.async.commit_group;" ::: "memory")
#define CP_WAIT0()  asm volatile("cp.async.wait_group 0;" ::: "memory")

#define LDSM_X4(r0, r1, r2, r3, addr)                                   \
    asm volatile("ldmatrix.sync.aligned.m8n8.x4.shared.b16 "            \
                 "{%0,%1,%2,%3}, [%4];"                                 \
                 : "=r"(r0), "=r"(r1), "=r"(r2), "=r"(r3) : "r"(addr))

#define LDSM_X4_T(r0, r1, r2, r3, addr)                                 \
    asm volatile("ldmatrix.sync.aligned.m8n8.x4.trans.shared.b16 "      \
                 "{%0,%1,%2,%3}, [%4];"                                 \
                 : "=r"(r0), "=r"(r1), "=r"(r2), "=r"(r3) : "r"(addr))

__device__ __forceinline__ void mma_f16(float* c, const uint32_t* a,
                                        const uint32_t* b) {
    asm volatile(
        "mma.sync.aligned.m16n8k16.row.col.f32.f16.f16.f32 "
        "{%0,%1,%2,%3}, {%4,%5,%6,%7}, {%8,%9}, {%0,%1,%2,%3};"
        : "+f"(c[0]), "+f"(c[1]), "+f"(c[2]), "+f"(c[3])
        : "r"(a[0]), "r"(a[1]), "r"(a[2]), "r"(a[3]), "r"(b[0]), "r"(b[1]));
}

// ---------------------------------------------------------------------------
// Tile loaders (cp.async 16B), 256-thread versions (qkt/av)
// ---------------------------------------------------------------------------
// 128 rows x 64 halves, stride SA
__device__ __forceinline__ void load_tile_k(__half* dst,
                                            const __half* __restrict__ gsrc,
                                            int ldh, int tid) {
    unsigned long long gb = (unsigned long long)__cvta_generic_to_global(gsrc);
    #pragma unroll
    for (int i = 0; i < 4; ++i) {
        int ch  = i * 256 + tid;           // 0..1023
        int row = ch >> 3;
        int off = ch & 7;
        uint32_t d = smem_u32(dst + row * SA + off * 8);
        unsigned long long s = gb + (unsigned long long)row * ((size_t)ldh * 2)
                                  + (unsigned)off * 16;
        CP_ASYNC16(d, s);
    }
}

// 64 rows x 128 halves, stride SBT (trans B: rows = k)
__device__ __forceinline__ void load_tile_t(__half* dst,
                                            const __half* __restrict__ gsrc,
                                            int ldh, int tid) {
    unsigned long long gb = (unsigned long long)__cvta_generic_to_global(gsrc);
    #pragma unroll
    for (int i = 0; i < 4; ++i) {
        int ch  = i * 256 + tid;           // 0..1023
        int row = ch >> 4;
        int off = ch & 15;
        uint32_t d = smem_u32(dst + row * SBT + off * 8);
        unsigned long long s = gb + (unsigned long long)row * ((size_t)ldh * 2)
                                  + (unsigned)off * 16;
        CP_ASYNC16(d, s);
    }
}

// ---------------------------------------------------------------------------
// One BKH=64 chunk for a 64x32 warp tile (4 ks x 4 mt x 4 nt), ks staggered
// by warp parity to break the post-barrier convoy.
// ---------------------------------------------------------------------------
template <bool TRB>
__device__ __forceinline__ void compute_chunk(const __half* As, const __half* Bs,
                                              float c[4][4][4],
                                              int wr, int wc, int lane, int wid) {
    const int arow  = lane & 15;
    const int asel  = (lane >> 4) * 8;
    const int bn    = (lane & 7) + ((lane >> 4) << 3);    // NT path
    const int bsel  = ((lane >> 3) & 1) * 8;
    const int tkrow = (lane & 7) + ((lane >> 3) & 1) * 8; // TR path
    const int tnoff = (lane >> 4) * 8;
    const int ks0   = (wid & 1) << 1;
    #pragma unroll
    for (int ksi = 0; ksi < 4; ++ksi) {
        const int ks = (ksi + ks0) & 3;
        const int kh = ks * 16;
        uint32_t a[4][4], b[4][2];
        #pragma unroll
        for (int mt = 0; mt < 4; ++mt) {
            uint32_t ad = smem_u32(As + (wr * 64 + mt * 16 + arow) * SA + kh + asel);
            LDSM_X4(a[mt][0], a[mt][1], a[mt][2], a[mt][3], ad);
        }
        #pragma unroll
        for (int np = 0; np < 2; ++np) {
            uint32_t r0, r1, r2, r3;
            if (!TRB) {
                uint32_t ad = smem_u32(Bs + (wc * 32 + np * 16 + bn) * SA + kh + bsel);
                LDSM_X4(r0, r1, r2, r3, ad);
            } else {
                uint32_t ad = smem_u32(Bs + (kh + tkrow) * SBT
                                          + wc * 32 + np * 16 + tnoff);
                LDSM_X4_T(r0, r1, r2, r3, ad);
            }
            b[np * 2][0] = r0;     b[np * 2][1] = r1;
            b[np * 2 + 1][0] = r2; b[np * 2 + 1][1] = r3;
        }
        #pragma unroll
        for (int mt = 0; mt < 4; ++mt)
            #pragma unroll
            for (int nt = 0; nt < 4; ++nt)
                mma_f16(c[mt][nt], a[mt], b[nt]);
    }
}

// Double-buffered mainloop (qkt/av): C[128x128] += A[128,K] . op(B)
template <bool TRB>
__device__ __forceinline__ void gemm_mainloop(__half* smem,
                                              const __half* __restrict__ A, int lda,
                                              const __half* __restrict__ B, int ldb,
                                              int nc, int tid,
                                              float c[4][4][4],
                                              int wr, int wc, int lane, int wid) {
    __half* As0 = smem;
    __half* Bs0 = smem + AHALVES;
    __half* As1 = smem + STAGEH;
    __half* Bs1 = smem + STAGEH + AHALVES;

    load_tile_k(As0, A, lda, tid);
    if (TRB) load_tile_t(Bs0, B, ldb, tid);
    else     load_tile_k(Bs0, B, ldb, tid);
    CP_COMMIT();

    for (int ch = 0; ch < nc; ++ch) {
        const int buf = ch & 1;
        CP_WAIT0();
        __syncthreads();
        if (ch + 1 < nc) {
            __half* An = buf ? As0 : As1;
            __half* Bn = buf ? Bs0 : Bs1;
            load_tile_k(An, A + (size_t)(ch + 1) * BKH, lda, tid);
            if (TRB) load_tile_t(Bn, B + (size_t)(ch + 1) * BKH * ldb, ldb, tid);
            else     load_tile_k(Bn, B + (size_t)(ch + 1) * BKH, ldb, tid);
            CP_COMMIT();
        }
        compute_chunk<TRB>(buf ? As1 : As0, (buf ? As1 : As0) + AHALVES,
                           c, wr, wc, lane, wid);
    }
}

__device__ __forceinline__ void zero_acc(float c[4][4][4]) {
    #pragma unroll
    for (int i = 0; i < 4; ++i)
        #pragma unroll
        for (int j = 0; j < 4; ++j)
            #pragma unroll
            for (int k = 0; k < 4; ++k) c[i][j][k] = 0.0f;
}

// ---------------------------------------------------------------------------
// A-stationary projection kernel: 512 CTAs x 128 threads (4 warps).
// Each CTA holds a 64-row x-block resident in smem and streams all 12
// B-tiles (3 matrices x 4 column tiles) through a double-buffered slot.
// ---------------------------------------------------------------------------
__global__ __launch_bounds__(128) void proj_as(const float* __restrict__ bq,
                                               const float* __restrict__ bk,
                                               const float* __restrict__ bv) {
    extern __shared__ __half smem[];
    __half* Ar  = smem;                     // resident A: 64 x SAW
    __half* Bb0 = smem + PA_HALVES;
    __half* Bb1 = Bb0 + PB_HALVES;

    const int tid = threadIdx.x, lane = tid & 31, wc = tid >> 5;  // wc 0..3
    const int rowT = blockIdx.x;            // 64-row block index (0..511)

    const __half* Agm = g_xh + (size_t)rowT * 64 * EE;
    __half* outs[3] = {g_Qh, g_Kh, g_Vh};
    const float* biases[3] = {bq, bk, bv};

    // --- Load resident A: 64 rows x 512 halves (1024 B/row = 64 x 16B/row)
    //     = 4096 chunks total: row = ch>>6, off = ch&63.
    {
        unsigned long long gb = (unsigned long long)__cvta_generic_to_global(Agm);
        #pragma unroll
        for (int i = 0; i < 32; ++i) {
            int ch  = i * 128 + tid;        // 0..4095
            int row = ch >> 6;              // 0..63
            int off = ch & 63;              // 16B chunk within row, 0..63
            uint32_t d = smem_u32(Ar + row * SAW + off * 8);
            unsigned long long s = gb + (unsigned long long)row * (EE * 2)
                                      + (unsigned)off * 16;
            CP_ASYNC16(d, s);
        }
        CP_COMMIT();
    }

    // --- B chunk loader: 64 k-rows x 128 halves, stride SBT, 128 threads ---
    auto load_b = [&](__half* dst, const __half* gsrc) {
        unsigned long long gb = (unsigned long long)__cvta_generic_to_global(gsrc);
        #pragma unroll
        for (int i = 0; i < 8; ++i) {
            int ch  = i * 128 + tid;        // 0..1023
            int row = ch >> 4;
            int off = ch & 15;
            uint32_t d = smem_u32(dst + row * SBT + off * 8);
            unsigned long long s = gb + (unsigned long long)row * (KK * 2)
                                      + (unsigned)off * 16;
            CP_ASYNC16(d, s);
        }
    };

    // Chunk c (0..95): tile = c>>3 (which = tile>>2, colT = tile&3), kc = c&7
    auto b_src = [&](int c) -> const __half* {
        const int tile = c >> 3, kc = c & 7;
        return g_Wh + (size_t)(tile >> 2) * EE * KK + (tile & 3) * 128
                    + (size_t)kc * 64 * KK;
    };

    load_b(Bb0, b_src(0));
    CP_COMMIT();

    const int arow  = lane & 15;
    const int asel  = (lane >> 4) * 8;
    const int tkrow = (lane & 7) + ((lane >> 3) & 1) * 8;
    const int tnoff = (lane >> 4) * 8;
    const int g = lane >> 2, q = lane & 3;
    const int ks0 = (wc & 1) << 1;

    float c[4][4][4];
    zero_acc(c);

    for (int ch = 0; ch < 96; ++ch) {
        const int buf = ch & 1;
        CP_WAIT0();
        __syncthreads();
        if (ch + 1 < 96) {
            load_b(buf ? Bb0 : Bb1, b_src(ch + 1));
            CP_COMMIT();
        }
        const __half* Bs = buf ? Bb1 : Bb0;
        const int kbase = (ch & 7) * 64;    // A column base for this chunk

        #pragma unroll
        for (int ksi = 0; ksi < 4; ++ksi) {
            const int ks = (ksi + ks0) & 3;
            const int kh = ks * 16;
            uint32_t a[4][4], b[4][2];
            #pragma unroll
            for (int mt = 0; mt < 4; ++mt) {
                uint32_t ad = smem_u32(Ar + (mt * 16 + arow) * SAW
                                          + kbase + kh + asel);
                LDSM_X4(a[mt][0], a[mt][1], a[mt][2], a[mt][3], ad);
            }
            #pragma unroll
            for (int np = 0; np < 2; ++np) {
                uint32_t r0, r1, r2, r3;
                uint32_t ad = smem_u32(Bs + (kh + tkrow) * SBT
                                          + wc * 32 + np * 16 + tnoff);
                LDSM_X4_T(r0, r1, r2, r3, ad);
                b[np * 2][0] = r0;     b[np * 2][1] = r1;
                b[np * 2 + 1][0] = r2; b[np * 2 + 1][1] = r3;
            }
            #pragma unroll
            for (int mt = 0; mt < 4; ++mt)
                #pragma unroll
                for (int nt = 0; nt < 4; ++nt)
                    mma_f16(c[mt][nt], a[mt], b[nt]);
        }

        if ((ch & 7) == 7) {   // end of tile -> epilogue, reset accumulators
            const int tile = ch >> 3;
            const int which = tile >> 2, colT = tile & 3;
            __half* Crow = outs[which] + (size_t)rowT * 64 * KK;
            const float* bias = biases[which];
            #pragma unroll
            for (int mt = 0; mt < 4; ++mt) {
                #pragma unroll
                for (int nt = 0; nt < 4; ++nt) {
                    const int row = mt * 16 + g;
                    const int col = colT * 128 + wc * 32 + nt * 8 + q * 2;
                    float b0 = __ldg(bias + col), b1 = __ldg(bias + col + 1);
                    *(__half2*)&Crow[(size_t)row * KK + col] =
                        __floats2half2_rn(c[mt][nt][0] + b0, c[mt][nt][1] + b1);
                    *(__half2*)&Crow[(size_t)(row + 8) * KK + col] =
                        __floats2half2_rn(c[mt][nt][2] + b0, c[mt][nt][3] + b1);
                }
            }
            zero_acc(c);
        }
    }
}

// ---------------------------------------------------------------------------
// qkt / av kernels (R6-proven shape: 256 threads, 128x128 CTA tile)
// ---------------------------------------------------------------------------
__constant__ int PT[10] = {0, 1, 1, 2, 2, 2, 3, 3, 3, 3};
__constant__ int PS[10] = {0, 0, 1, 0, 1, 2, 0, 1, 2, 3};

__global__ __launch_bounds__(256) void qkt_mma() {
    extern __shared__ __half smem[];
    const int tid = threadIdx.x, lane = tid & 31, wid = tid >> 5;
    const int wr = wid >> 2, wc = wid & 3;
    const int tT = PT[blockIdx.x], sT = PS[blockIdx.x], b = blockIdx.y;

    const __half* A = g_Qh + (size_t)b * TT * KK + (size_t)tT * 128 * KK;
    const __half* B = g_Kh + (size_t)b * TT * KK + (size_t)sT * 128 * KK;

    float c[4][4][4];
    zero_acc(c);
    gemm_mainloop<false>(smem, A, KK, B, KK, KK / BKH, tid, c, wr, wc, lane, wid);

    const float SCALE = 0.04419417382415922f;   // 1/sqrt(512)
    float* Crow = g_S + (size_t)b * TT * TT + (size_t)tT * 128 * TT;
    const int g = lane >> 2, q = lane & 3;
    #pragma unroll
    for (int mt = 0; mt < 4; ++mt) {
        #pragma unroll
        for (int nt = 0; nt < 4; ++nt) {
            const int row = wr * 64 + mt * 16 + g;
            const int col = sT * 128 + wc * 32 + nt * 8 + q * 2;
            *(float2*)&Crow[(size_t)row * TT + col] =
                make_float2(c[mt][nt][0] * SCALE, c[mt][nt][1] * SCALE);
            *(float2*)&Crow[(size_t)(row + 8) * TT + col] =
                make_float2(c[mt][nt][2] * SCALE, c[mt][nt][3] * SCALE);
        }
    }
}

__global__ __launch_bounds__(256) void av_mma(float* __restrict__ out) {
    extern __shared__ __half smem[];
    const int tid = threadIdx.x, lane = tid & 31, wid = tid >> 5;
    const int wr = wid >> 2, wc = wid & 3;
    const int vT = blockIdx.x, tT = 3 - blockIdx.y, b = blockIdx.z;  // heavy first

    const __half* A = g_Sh + (size_t)b * TT * TT + (size_t)tT * 128 * TT;
    const __half* B = g_Vh + (size_t)b * TT * VV + vT * 128;
    const int nc = (tT + 1) * (128 / BKH);     // causal K cutoff

    float c[4][4][4];
    zero_acc(c);
    gemm_mainloop<true>(smem, A, TT, B, VV, nc, tid, c, wr, wc, lane, wid);

    float* Crow = out + (size_t)b * TT * VV + (size_t)tT * 128 * VV;
    const int g = lane >> 2, q = lane & 3;
    #pragma unroll
    for (int mt = 0; mt < 4; ++mt) {
        #pragma unroll
        for (int nt = 0; nt < 4; ++nt) {
            const int row = wr * 64 + mt * 16 + g;
            const int col = vT * 128 + wc * 32 + nt * 8 + q * 2;
            *(float2*)&Crow[(size_t)row * VV + col] =
                make_float2(c[mt][nt][0], c[mt][nt][1]);
            *(float2*)&Crow[(size_t)(row + 8) * VV + col] =
                make_float2(c[mt][nt][2], c[mt][nt][3]);
        }
    }
}

// ---------------------------------------------------------------------------
// Aux kernels
// ---------------------------------------------------------------------------
__global__ __launch_bounds__(256) void convx_kernel(const float* __restrict__ x) {
    size_t i = ((size_t)blockIdx.x * 256 + threadIdx.x) * 4;
    float4 v = *(const float4*)(x + i);
    __half2* d = (__half2*)(g_xh + i);
    d[0] = __floats2half2_rn(v.x, v.y);
    d[1] = __floats2half2_rn(v.z, v.w);
}

__global__ __launch_bounds__(256) void convw_kernel(const float* __restrict__ Wq,
                                                    const float* __restrict__ Wk,
                                                    const float* __restrict__ Wv) {
    const int which = blockIdx.y;
    const float* W = (which == 0) ? Wq : ((which == 1) ? Wk : Wv);
    __half* D = g_Wh + (size_t)which * EE * KK;
    size_t i = ((size_t)blockIdx.x * 256 + threadIdx.x) * 4;
    float4 v = *(const float4*)(W + i);
    __half2* d = (__half2*)(D + i);
    d[0] = __floats2half2_rn(v.x, v.y);
    d[1] = __floats2half2_rn(v.z, v.w);
}

// Column softmax (axis = t), online max/sum. One thread per column s.
__global__ __launch_bounds__(128) void softmax_kernel() {
    const int b = blockIdx.y;
    const int s = blockIdx.x * 128 + threadIdx.x;
    const float* Sb = g_S + (size_t)b * TT * TT;
    __half* Sh = g_Sh + (size_t)b * TT * TT;
    const int tile0 = blockIdx.x * 128;
    const int w0 = tile0 + (threadIdx.x & ~31);

    float m = -1e30f, sum = 0.0f;
    #pragma unroll 2
    for (int t = w0; t < TT; ++t) {
        float xv = Sb[(size_t)t * TT + s];
        if (t >= s) {
            float nm = fmaxf(m, xv);
            sum = sum * __expf(m - nm) + __expf(xv - nm);
            m = nm;
        }
    }
    const float inv = 1.0f / sum;
    #pragma unroll 4
    for (int t = tile0; t < TT; ++t) {
        float r = 0.0f;
        if (t >= s) r = __expf(Sb[(size_t)t * TT + s] - m) * inv;
        Sh[(size_t)t * TT + s] = __float2half(r);
    }
}

// ---------------------------------------------------------------------------
extern "C" void kernel_launch(void* const* d_in, const int* in_sizes, int n_in,
                              void* d_out, int out_size) {
    const float* x  = (const float*)d_in[0];
    const float* Wq = (const float*)d_in[1];
    const float* bq = (const float*)d_in[2];
    const float* Wk = (const float*)d_in[3];
    const float* bk = (const float*)d_in[4];
    const float* Wv = (const float*)d_in[5];
    const float* bv = (const float*)d_in[6];
    float* out = (float*)d_out;

    cudaFuncSetAttribute(proj_as, cudaFuncAttributeMaxDynamicSharedMemorySize, PROJ_SMEM);
    cudaFuncSetAttribute(qkt_mma, cudaFuncAttributeMaxDynamicSharedMemorySize, SMEM_BYTES);
    cudaFuncSetAttribute(av_mma,  cudaFuncAttributeMaxDynamicSharedMemorySize, SMEM_BYTES);

    convx_kernel<<<(NB * TT * EE) / (256 * 4), 256>>>(x);
    convw_kernel<<<dim3((EE * KK) / (256 * 4), 3), 256>>>(Wq, Wk, Wv);
    proj_as     <<<512, 128, PROJ_SMEM>>>(bq, bk, bv);
    qkt_mma     <<<dim3(10, 64), 256, SMEM_BYTES>>>();
    softmax_kernel<<<dim3(4, 64), 128>>>();
    av_mma      <<<dim3(4, 4, 64), 256, SMEM_BYTES>>>(out);
}

// round 12
// speedup vs baseline: 1.0627x; 1.0627x over previous
#include <cuda_runtime.h>
#include <cuda_fp16.h>
#include <cstdint>
#include <math.h>

#define NB 64
#define TT 512
#define EE 512
#define KK 512
#define VV 512
#define BKH 64                  // K halves per chunk
#define SA  72                  // A / NT-B smem row stride (64 + 8 pad)
#define SBT 136                 // trans-B smem row stride (128 + 8 pad)

#define AHALVES (128 * SA)                  // 9216 halves
#define BHALVES (128 * SA)
#define STAGEH  (AHALVES + BHALVES)         // 18432 halves = 36864 B
#define SMEM_BYTES (2 * STAGEH * 2)         // 73728 B

// ---------------------------------------------------------------------------
// Device scratch
// ---------------------------------------------------------------------------
__device__ __half g_xh[(size_t)NB * TT * EE];
__device__ __half g_Wh[(size_t)3 * EE * KK];    // W natural [e][k] fp16
__device__ __half g_Qh[(size_t)NB * TT * KK];
__device__ __half g_Kh[(size_t)NB * TT * KK];
__device__ __half g_Vh[(size_t)NB * TT * VV];   // V natural [t][v] fp16
__device__ float  g_S [(size_t)NB * TT * TT];
__device__ __half g_Sh[(size_t)NB * TT * TT];

// ---------------------------------------------------------------------------
// Helpers
// ---------------------------------------------------------------------------
__device__ __forceinline__ uint32_t smem_u32(const void* p) {
    uint32_t a;
    asm("{ .reg .u64 t; cvta.to.shared.u64 t, %1; cvt.u32.u64 %0, t; }"
        : "=r"(a) : "l"(p));
    return a;
}

#define CP_ASYNC16(dst, src) \
    asm volatile("cp.async.cg.shared.global [%0], [%1], 16;" \
                 :: "r"(dst), "l"(src) : "memory")
#define CP_COMMIT() asm volatile("cp.async.commit_group;" ::: "memory")
#define CP_WAIT0()  asm volatile("cp.async.wait_group 0;" ::: "memory")

#define LDSM_X4(r0, r1, r2, r3, addr)                                   \
    asm volatile("ldmatrix.sync.aligned.m8n8.x4.shared.b16 "            \
                 "{%0,%1,%2,%3}, [%4];"                                 \
                 : "=r"(r0), "=r"(r1), "=r"(r2), "=r"(r3) : "r"(addr))

#define LDSM_X4_T(r0, r1, r2, r3, addr)                                 \
    asm volatile("ldmatrix.sync.aligned.m8n8.x4.trans.shared.b16 "      \
                 "{%0,%1,%2,%3}, [%4];"                                 \
                 : "=r"(r0), "=r"(r1), "=r"(r2), "=r"(r3) : "r"(addr))

__device__ __forceinline__ void mma_f16(float* c, const uint32_t* a,
                                        const uint32_t* b) {
    asm volatile(
        "mma.sync.aligned.m16n8k16.row.col.f32.f16.f16.f32 "
        "{%0,%1,%2,%3}, {%4,%5,%6,%7}, {%8,%9}, {%0,%1,%2,%3};"
        : "+f"(c[0]), "+f"(c[1]), "+f"(c[2]), "+f"(c[3])
        : "r"(a[0]), "r"(a[1]), "r"(a[2]), "r"(a[3]), "r"(b[0]), "r"(b[1]));
}

// ---------------------------------------------------------------------------
// Tile loaders (cp.async 16B)
// ---------------------------------------------------------------------------
// 128 rows x 64 halves, stride SA
__device__ __forceinline__ void load_tile_k(__half* dst,
                                            const __half* __restrict__ gsrc,
                                            int ldh, int tid) {
    unsigned long long gb = (unsigned long long)__cvta_generic_to_global(gsrc);
    #pragma unroll
    for (int i = 0; i < 4; ++i) {
        int ch  = i * 256 + tid;           // 0..1023
        int row = ch >> 3;
        int off = ch & 7;
        uint32_t d = smem_u32(dst + row * SA + off * 8);
        unsigned long long s = gb + (unsigned long long)row * ((size_t)ldh * 2)
                                  + (unsigned)off * 16;
        CP_ASYNC16(d, s);
    }
}

// 64 rows x 128 halves, stride SBT (trans B: rows = k)
__device__ __forceinline__ void load_tile_t(__half* dst,
                                            const __half* __restrict__ gsrc,
                                            int ldh, int tid) {
    unsigned long long gb = (unsigned long long)__cvta_generic_to_global(gsrc);
    #pragma unroll
    for (int i = 0; i < 4; ++i) {
        int ch  = i * 256 + tid;           // 0..1023
        int row = ch >> 4;
        int off = ch & 15;
        uint32_t d = smem_u32(dst + row * SBT + off * 8);
        unsigned long long s = gb + (unsigned long long)row * ((size_t)ldh * 2)
                                  + (unsigned)off * 16;
        CP_ASYNC16(d, s);
    }
}

// ---------------------------------------------------------------------------
// One BKH=64 chunk for a 64x32 warp tile (4 ks x 4 mt x 4 nt), ks staggered
// by warp parity to break the post-barrier convoy.
// ---------------------------------------------------------------------------
template <bool TRB>
__device__ __forceinline__ void compute_chunk(const __half* As, const __half* Bs,
                                              float c[4][4][4],
                                              int wr, int wc, int lane, int wid) {
    const int arow  = lane & 15;
    const int asel  = (lane >> 4) * 8;
    const int bn    = (lane & 7) + ((lane >> 4) << 3);    // NT path
    const int bsel  = ((lane >> 3) & 1) * 8;
    const int tkrow = (lane & 7) + ((lane >> 3) & 1) * 8; // TR path
    const int tnoff = (lane >> 4) * 8;
    const int ks0   = (wid & 1) << 1;
    #pragma unroll
    for (int ksi = 0; ksi < 4; ++ksi) {
        const int ks = (ksi + ks0) & 3;
        const int kh = ks * 16;
        uint32_t a[4][4], b[4][2];
        #pragma unroll
        for (int mt = 0; mt < 4; ++mt) {
            uint32_t ad = smem_u32(As + (wr * 64 + mt * 16 + arow) * SA + kh + asel);
            LDSM_X4(a[mt][0], a[mt][1], a[mt][2], a[mt][3], ad);
        }
        #pragma unroll
        for (int np = 0; np < 2; ++np) {
            uint32_t r0, r1, r2, r3;
            if (!TRB) {
                uint32_t ad = smem_u32(Bs + (wc * 32 + np * 16 + bn) * SA + kh + bsel);
                LDSM_X4(r0, r1, r2, r3, ad);
            } else {
                uint32_t ad = smem_u32(Bs + (kh + tkrow) * SBT
                                          + wc * 32 + np * 16 + tnoff);
                LDSM_X4_T(r0, r1, r2, r3, ad);
            }
            b[np * 2][0] = r0;     b[np * 2][1] = r1;
            b[np * 2 + 1][0] = r2; b[np * 2 + 1][1] = r3;
        }
        #pragma unroll
        for (int mt = 0; mt < 4; ++mt)
            #pragma unroll
            for (int nt = 0; nt < 4; ++nt)
                mma_f16(c[mt][nt], a[mt], b[nt]);
    }
}

// Double-buffered mainloop: C[128x128] += A[128,K] . op(B)
template <bool TRB>
__device__ __forceinline__ void gemm_mainloop(__half* smem,
                                              const __half* __restrict__ A, int lda,
                                              const __half* __restrict__ B, int ldb,
                                              int nc, int tid,
                                              float c[4][4][4],
                                              int wr, int wc, int lane, int wid) {
    __half* As0 = smem;
    __half* Bs0 = smem + AHALVES;
    __half* As1 = smem + STAGEH;
    __half* Bs1 = smem + STAGEH + AHALVES;

    load_tile_k(As0, A, lda, tid);
    if (TRB) load_tile_t(Bs0, B, ldb, tid);
    else     load_tile_k(Bs0, B, ldb, tid);
    CP_COMMIT();

    for (int ch = 0; ch < nc; ++ch) {
        const int buf = ch & 1;
        CP_WAIT0();
        __syncthreads();
        if (ch + 1 < nc) {
            __half* An = buf ? As0 : As1;
            __half* Bn = buf ? Bs0 : Bs1;
            load_tile_k(An, A + (size_t)(ch + 1) * BKH, lda, tid);
            if (TRB) load_tile_t(Bn, B + (size_t)(ch + 1) * BKH * ldb, ldb, tid);
            else     load_tile_k(Bn, B + (size_t)(ch + 1) * BKH, ldb, tid);
            CP_COMMIT();
        }
        compute_chunk<TRB>(buf ? As1 : As0, (buf ? As1 : As0) + AHALVES,
                           c, wr, wc, lane, wid);
    }
}

__device__ __forceinline__ void zero_acc(float c[4][4][4]) {
    #pragma unroll
    for (int i = 0; i < 4; ++i)
        #pragma unroll
        for (int j = 0; j < 4; ++j)
            #pragma unroll
            for (int k = 0; k < 4; ++k) c[i][j][k] = 0.0f;
}

// ---------------------------------------------------------------------------
// Projections: out = x @ W + b (W natural layout, TRB path).
// Grid dim3(12, 256): x fuses (which, colT) so all 12 CTAs sharing an A
// row-tile launch adjacently -> A is fetched from DRAM once and served from
// L2 for the other 11 (A DRAM traffic 402 MB -> ~34 MB).
// ---------------------------------------------------------------------------
__global__ __launch_bounds__(256) void proj_mma(const float* __restrict__ bq,
                                                const float* __restrict__ bk,
                                                const float* __restrict__ bv) {
    extern __shared__ __half smem[];
    const int tid = threadIdx.x, lane = tid & 31, wid = tid >> 5;
    const int wr = wid >> 2, wc = wid & 3;
    const int which = blockIdx.x >> 2, colT = blockIdx.x & 3;
    const int rowT = blockIdx.y;

    const __half* A = g_xh + (size_t)rowT * 128 * EE;
    const __half* B = g_Wh + (size_t)which * EE * KK + colT * 128;
    __half* Cmat = (which == 0) ? g_Qh : ((which == 1) ? g_Kh : g_Vh);
    const float* bias = (which == 0) ? bq : ((which == 1) ? bk : bv);

    float c[4][4][4];
    zero_acc(c);
    gemm_mainloop<true>(smem, A, EE, B, KK, EE / BKH, tid, c, wr, wc, lane, wid);

    __half* Crow = Cmat + (size_t)rowT * 128 * KK;
    const int g = lane >> 2, q = lane & 3;
    #pragma unroll
    for (int mt = 0; mt < 4; ++mt) {
        #pragma unroll
        for (int nt = 0; nt < 4; ++nt) {
            const int row = wr * 64 + mt * 16 + g;
            const int col = colT * 128 + wc * 32 + nt * 8 + q * 2;
            float b0 = __ldg(bias + col), b1 = __ldg(bias + col + 1);
            *(__half2*)&Crow[(size_t)row * KK + col] =
                __floats2half2_rn(c[mt][nt][0] + b0, c[mt][nt][1] + b1);
            *(__half2*)&Crow[(size_t)(row + 8) * KK + col] =
                __floats2half2_rn(c[mt][nt][2] + b0, c[mt][nt][3] + b1);
        }
    }
}

// ---------------------------------------------------------------------------
// qkt / av kernels (proven shape: 256 threads, 128x128 CTA tile)
// ---------------------------------------------------------------------------
__constant__ int PT[10] = {0, 1, 1, 2, 2, 2, 3, 3, 3, 3};
__constant__ int PS[10] = {0, 0, 1, 0, 1, 2, 0, 1, 2, 3};

__global__ __launch_bounds__(256) void qkt_mma() {
    extern __shared__ __half smem[];
    const int tid = threadIdx.x, lane = tid & 31, wid = tid >> 5;
    const int wr = wid >> 2, wc = wid & 3;
    const int tT = PT[blockIdx.x], sT = PS[blockIdx.x], b = blockIdx.y;

    const __half* A = g_Qh + (size_t)b * TT * KK + (size_t)tT * 128 * KK;
    const __half* B = g_Kh + (size_t)b * TT * KK + (size_t)sT * 128 * KK;

    float c[4][4][4];
    zero_acc(c);
    gemm_mainloop<false>(smem, A, KK, B, KK, KK / BKH, tid, c, wr, wc, lane, wid);

    const float SCALE = 0.04419417382415922f;   // 1/sqrt(512)
    float* Crow = g_S + (size_t)b * TT * TT + (size_t)tT * 128 * TT;
    const int g = lane >> 2, q = lane & 3;
    #pragma unroll
    for (int mt = 0; mt < 4; ++mt) {
        #pragma unroll
        for (int nt = 0; nt < 4; ++nt) {
            const int row = wr * 64 + mt * 16 + g;
            const int col = sT * 128 + wc * 32 + nt * 8 + q * 2;
            *(float2*)&Crow[(size_t)row * TT + col] =
                make_float2(c[mt][nt][0] * SCALE, c[mt][nt][1] * SCALE);
            *(float2*)&Crow[(size_t)(row + 8) * TT + col] =
                make_float2(c[mt][nt][2] * SCALE, c[mt][nt][3] * SCALE);
        }
    }
}

__global__ __launch_bounds__(256) void av_mma(float* __restrict__ out) {
    extern __shared__ __half smem[];
    const int tid = threadIdx.x, lane = tid & 31, wid = tid >> 5;
    const int wr = wid >> 2, wc = wid & 3;
    const int vT = blockIdx.x, tT = 3 - blockIdx.y, b = blockIdx.z;  // heavy first

    const __half* A = g_Sh + (size_t)b * TT * TT + (size_t)tT * 128 * TT;
    const __half* B = g_Vh + (size_t)b * TT * VV + vT * 128;
    const int nc = (tT + 1) * (128 / BKH);     // causal K cutoff

    float c[4][4][4];
    zero_acc(c);
    gemm_mainloop<true>(smem, A, TT, B, VV, nc, tid, c, wr, wc, lane, wid);

    float* Crow = out + (size_t)b * TT * VV + (size_t)tT * 128 * VV;
    const int g = lane >> 2, q = lane & 3;
    #pragma unroll
    for (int mt = 0; mt < 4; ++mt) {
        #pragma unroll
        for (int nt = 0; nt < 4; ++nt) {
            const int row = wr * 64 + mt * 16 + g;
            const int col = vT * 128 + wc * 32 + nt * 8 + q * 2;
            *(float2*)&Crow[(size_t)row * VV + col] =
                make_float2(c[mt][nt][0], c[mt][nt][1]);
            *(float2*)&Crow[(size_t)(row + 8) * VV + col] =
                make_float2(c[mt][nt][2], c[mt][nt][3]);
        }
    }
}

// ---------------------------------------------------------------------------
// Aux kernels
// ---------------------------------------------------------------------------
__global__ __launch_bounds__(256) void convx_kernel(const float* __restrict__ x) {
    size_t i = ((size_t)blockIdx.x * 256 + threadIdx.x) * 4;
    float4 v = *(const float4*)(x + i);
    __half2* d = (__half2*)(g_xh + i);
    d[0] = __floats2half2_rn(v.x, v.y);
    d[1] = __floats2half2_rn(v.z, v.w);
}

__global__ __launch_bounds__(256) void convw_kernel(const float* __restrict__ Wq,
                                                    const float* __restrict__ Wk,
                                                    const float* __restrict__ Wv) {
    const int which = blockIdx.y;
    const float* W = (which == 0) ? Wq : ((which == 1) ? Wk : Wv);
    __half* D = g_Wh + (size_t)which * EE * KK;
    size_t i = ((size_t)blockIdx.x * 256 + threadIdx.x) * 4;
    float4 v = *(const float4*)(W + i);
    __half2* d = (__half2*)(D + i);
    d[0] = __floats2half2_rn(v.x, v.y);
    d[1] = __floats2half2_rn(v.z, v.w);
}

// Column softmax (axis = t), online max/sum. One thread per column s.
__global__ __launch_bounds__(128) void softmax_kernel() {
    const int b = blockIdx.y;
    const int s = blockIdx.x * 128 + threadIdx.x;
    const float* Sb = g_S + (size_t)b * TT * TT;
    __half* Sh = g_Sh + (size_t)b * TT * TT;
    const int tile0 = blockIdx.x * 128;
    const int w0 = tile0 + (threadIdx.x & ~31);

    float m = -1e30f, sum = 0.0f;
    #pragma unroll 2
    for (int t = w0; t < TT; ++t) {
        float xv = Sb[(size_t)t * TT + s];
        if (t >= s) {
            float nm = fmaxf(m, xv);
            sum = sum * __expf(m - nm) + __expf(xv - nm);
            m = nm;
        }
    }
    const float inv = 1.0f / sum;
    #pragma unroll 4
    for (int t = tile0; t < TT; ++t) {
        float r = 0.0f;
        if (t >= s) r = __expf(Sb[(size_t)t * TT + s] - m) * inv;
        Sh[(size_t)t * TT + s] = __float2half(r);
    }
}

// ---------------------------------------------------------------------------
extern "C" void kernel_launch(void* const* d_in, const int* in_sizes, int n_in,
                              void* d_out, int out_size) {
    const float* x  = (const float*)d_in[0];
    const float* Wq = (const float*)d_in[1];
    const float* bq = (const float*)d_in[2];
    const float* Wk = (const float*)d_in[3];
    const float* bk = (const float*)d_in[4];
    const float* Wv = (const float*)d_in[5];
    const float* bv = (const float*)d_in[6];
    float* out = (float*)d_out;

    cudaFuncSetAttribute(proj_mma, cudaFuncAttributeMaxDynamicSharedMemorySize, SMEM_BYTES);
    cudaFuncSetAttribute(qkt_mma,  cudaFuncAttributeMaxDynamicSharedMemorySize, SMEM_BYTES);
    cudaFuncSetAttribute(av_mma,   cudaFuncAttributeMaxDynamicSharedMemorySize, SMEM_BYTES);

    convx_kernel<<<(NB * TT * EE) / (256 * 4), 256>>>(x);
    convw_kernel<<<dim3((EE * KK) / (256 * 4), 3), 256>>>(Wq, Wk, Wv);
    proj_mma    <<<dim3(12, 256), 256, SMEM_BYTES>>>(bq, bk, bv);
    qkt_mma     <<<dim3(10, 64), 256, SMEM_BYTES>>>();
    softmax_kernel<<<dim3(4, 64), 128>>>();
    av_mma      <<<dim3(4, 4, 64), 256, SMEM_BYTES>>>(out);
}

// round 14
// speedup vs baseline: 1.1113x; 1.0457x over previous
#include <cuda_runtime.h>
#include <cuda_fp16.h>
#include <cstdint>
#include <math.h>

#define NB 64
#define TT 512
#define EE 512
#define KK 512
#define VV 512
#define BKH 64                  // K halves per chunk
#define SA  72                  // A / NT-B smem row stride (64 + 8 pad)
#define SBT 136                 // trans-B smem row stride (128 + 8 pad)

#define AHALVES (128 * SA)                  // 9216 halves
#define BHALVES (128 * SA)
#define STAGEH  (AHALVES + BHALVES)         // 18432 halves = 36864 B
#define SMEM_BYTES (2 * STAGEH * 2)         // 73728 B

// ---------------------------------------------------------------------------
// Device scratch
// ---------------------------------------------------------------------------
__device__ __half g_xh[(size_t)NB * TT * EE];
__device__ __half g_Wh[(size_t)3 * EE * KK];    // W natural [e][k] fp16
__device__ __half g_Qh[(size_t)NB * TT * KK];
__device__ __half g_Kh[(size_t)NB * TT * KK];
__device__ __half g_Vh[(size_t)NB * TT * VV];   // V natural [t][v] fp16
__device__ float  g_S [(size_t)NB * TT * TT];
__device__ __half g_Sh[(size_t)NB * TT * TT];

// ---------------------------------------------------------------------------
// Helpers
// ---------------------------------------------------------------------------
__device__ __forceinline__ uint32_t smem_u32(const void* p) {
    uint32_t a;
    asm("{ .reg .u64 t; cvta.to.shared.u64 t, %1; cvt.u32.u64 %0, t; }"
        : "=r"(a) : "l"(p));
    return a;
}

#define CP_ASYNC16(dst, src) \
    asm volatile("cp.async.cg.shared.global [%0], [%1], 16;" \
                 :: "r"(dst), "l"(src) : "memory")
#define CP_COMMIT() asm volatile("cp.async.commit_group;" ::: "memory")
#define CP_WAIT0()  asm volatile("cp.async.wait_group 0;" ::: "memory")

#define LDSM_X4(r0, r1, r2, r3, addr)                                   \
    asm volatile("ldmatrix.sync.aligned.m8n8.x4.shared.b16 "            \
                 "{%0,%1,%2,%3}, [%4];"                                 \
                 : "=r"(r0), "=r"(r1), "=r"(r2), "=r"(r3) : "r"(addr))

#define LDSM_X4_T(r0, r1, r2, r3, addr)                                 \
    asm volatile("ldmatrix.sync.aligned.m8n8.x4.trans.shared.b16 "      \
                 "{%0,%1,%2,%3}, [%4];"                                 \
                 : "=r"(r0), "=r"(r1), "=r"(r2), "=r"(r3) : "r"(addr))

__device__ __forceinline__ void mma_f16(float* c, const uint32_t* a,
                                        const uint32_t* b) {
    asm volatile(
        "mma.sync.aligned.m16n8k16.row.col.f32.f16.f16.f32 "
        "{%0,%1,%2,%3}, {%4,%5,%6,%7}, {%8,%9}, {%0,%1,%2,%3};"
        : "+f"(c[0]), "+f"(c[1]), "+f"(c[2]), "+f"(c[3])
        : "r"(a[0]), "r"(a[1]), "r"(a[2]), "r"(a[3]), "r"(b[0]), "r"(b[1]));
}

// ---------------------------------------------------------------------------
// Tile loaders (cp.async 16B), 128-thread versions
// ---------------------------------------------------------------------------
// 128 rows x 64 halves (128 B/row = 8 chunks/row), stride SA
__device__ __forceinline__ void load_tile_k(__half* dst,
                                            const __half* __restrict__ gsrc,
                                            int ldh, int tid) {
    unsigned long long gb = (unsigned long long)__cvta_generic_to_global(gsrc);
    #pragma unroll
    for (int i = 0; i < 8; ++i) {
        int ch  = i * 128 + tid;           // 0..1023
        int row = ch >> 3;
        int off = ch & 7;
        uint32_t d = smem_u32(dst + row * SA + off * 8);
        unsigned long long s = gb + (unsigned long long)row * ((size_t)ldh * 2)
                                  + (unsigned)off * 16;
        CP_ASYNC16(d, s);
    }
}

// 64 rows x 128 halves (256 B/row = 16 chunks/row), stride SBT (trans B)
__device__ __forceinline__ void load_tile_t(__half* dst,
                                            const __half* __restrict__ gsrc,
                                            int ldh, int tid) {
    unsigned long long gb = (unsigned long long)__cvta_generic_to_global(gsrc);
    #pragma unroll
    for (int i = 0; i < 8; ++i) {
        int ch  = i * 128 + tid;           // 0..1023
        int row = ch >> 4;
        int off = ch & 15;
        uint32_t d = smem_u32(dst + row * SBT + off * 8);
        unsigned long long s = gb + (unsigned long long)row * ((size_t)ldh * 2)
                                  + (unsigned)off * 16;
        CP_ASYNC16(d, s);
    }
}

// ---------------------------------------------------------------------------
// One BKH=64 chunk for a 64x64 warp tile: 4 ks x (4 A-ldsm + 4 B-ldsm +
// 32 MMAs). ks staggered by warp parity.
// ---------------------------------------------------------------------------
template <bool TRB>
__device__ __forceinline__ void compute_chunk(const __half* As, const __half* Bs,
                                              float c[4][8][4],
                                              int wr, int wc, int lane, int wid) {
    const int arow  = lane & 15;
    const int asel  = (lane >> 4) * 8;
    const int bn    = (lane & 7) + ((lane >> 4) << 3);    // NT path
    const int bsel  = ((lane >> 3) & 1) * 8;
    const int tkrow = (lane & 7) + ((lane >> 3) & 1) * 8; // TR path
    const int tnoff = (lane >> 4) * 8;
    const int ks0   = (wid & 1) << 1;
    #pragma unroll
    for (int ksi = 0; ksi < 4; ++ksi) {
        const int ks = (ksi + ks0) & 3;
        const int kh = ks * 16;
        uint32_t a[4][4], b[8][2];
        #pragma unroll
        for (int mt = 0; mt < 4; ++mt) {
            uint32_t ad = smem_u32(As + (wr * 64 + mt * 16 + arow) * SA + kh + asel);
            LDSM_X4(a[mt][0], a[mt][1], a[mt][2], a[mt][3], ad);
        }
        #pragma unroll
        for (int np = 0; np < 4; ++np) {
            uint32_t r0, r1, r2, r3;
            if (!TRB) {
                uint32_t ad = smem_u32(Bs + (wc * 64 + np * 16 + bn) * SA + kh + bsel);
                LDSM_X4(r0, r1, r2, r3, ad);
            } else {
                uint32_t ad = smem_u32(Bs + (kh + tkrow) * SBT
                                          + wc * 64 + np * 16 + tnoff);
                LDSM_X4_T(r0, r1, r2, r3, ad);
            }
            b[np * 2][0] = r0;     b[np * 2][1] = r1;
            b[np * 2 + 1][0] = r2; b[np * 2 + 1][1] = r3;
        }
        #pragma unroll
        for (int mt = 0; mt < 4; ++mt)
            #pragma unroll
            for (int nt = 0; nt < 8; ++nt)
                mma_f16(c[mt][nt], a[mt], b[nt]);
    }
}

// Double-buffered mainloop: C[128x128] += A[128,K] . op(B), 128 threads
template <bool TRB>
__device__ __forceinline__ void gemm_mainloop(__half* smem,
                                              const __half* __restrict__ A, int lda,
                                              const __half* __restrict__ B, int ldb,
                                              int nc, int tid,
                                              float c[4][8][4],
                                              int wr, int wc, int lane, int wid) {
    __half* As0 = smem;
    __half* Bs0 = smem + AHALVES;
    __half* As1 = smem + STAGEH;
    __half* Bs1 = smem + STAGEH + AHALVES;

    load_tile_k(As0, A, lda, tid);
    if (TRB) load_tile_t(Bs0, B, ldb, tid);
    else     load_tile_k(Bs0, B, ldb, tid);
    CP_COMMIT();

    for (int ch = 0; ch < nc; ++ch) {
        const int buf = ch & 1;
        CP_WAIT0();
        __syncthreads();
        if (ch + 1 < nc) {
            __half* An = buf ? As0 : As1;
            __half* Bn = buf ? Bs0 : Bs1;
            load_tile_k(An, A + (size_t)(ch + 1) * BKH, lda, tid);
            if (TRB) load_tile_t(Bn, B + (size_t)(ch + 1) * BKH * ldb, ldb, tid);
            else     load_tile_k(Bn, B + (size_t)(ch + 1) * BKH, ldb, tid);
            CP_COMMIT();
        }
        compute_chunk<TRB>(buf ? As1 : As0, (buf ? As1 : As0) + AHALVES,
                           c, wr, wc, lane, wid);
    }
}

__device__ __forceinline__ void zero_acc(float c[4][8][4]) {
    #pragma unroll
    for (int i = 0; i < 4; ++i)
        #pragma unroll
        for (int j = 0; j < 8; ++j)
            #pragma unroll
            for (int k = 0; k < 4; ++k) c[i][j][k] = 0.0f;
}

// ---------------------------------------------------------------------------
// GEMM kernels: 128 threads = 4 warps (wr 0..1, wc 0..1), warp tile 64x64,
// CTA tile 128x128, 2 CTAs/SM (regs ~180, smem 73.7KB).
// ---------------------------------------------------------------------------
__global__ __launch_bounds__(128) void proj_mma(const float* __restrict__ bq,
                                                const float* __restrict__ bk,
                                                const float* __restrict__ bv) {
    extern __shared__ __half smem[];
    const int tid = threadIdx.x, lane = tid & 31, wid = tid >> 5;
    const int wr = wid >> 1, wc = wid & 1;
    const int which = blockIdx.x >> 2, colT = blockIdx.x & 3;
    const int rowT = blockIdx.y;

    const __half* A = g_xh + (size_t)rowT * 128 * EE;
    const __half* B = g_Wh + (size_t)which * EE * KK + colT * 128;
    __half* Cmat = (which == 0) ? g_Qh : ((which == 1) ? g_Kh : g_Vh);
    const float* bias = (which == 0) ? bq : ((which == 1) ? bk : bv);

    float c[4][8][4];
    zero_acc(c);
    gemm_mainloop<true>(smem, A, EE, B, KK, EE / BKH, tid, c, wr, wc, lane, wid);

    __half* Crow = Cmat + (size_t)rowT * 128 * KK;
    const int g = lane >> 2, q = lane & 3;
    #pragma unroll
    for (int mt = 0; mt < 4; ++mt) {
        #pragma unroll
        for (int nt = 0; nt < 8; ++nt) {
            const int row = wr * 64 + mt * 16 + g;
            const int col = colT * 128 + wc * 64 + nt * 8 + q * 2;
            float b0 = __ldg(bias + col), b1 = __ldg(bias + col + 1);
            *(__half2*)&Crow[(size_t)row * KK + col] =
                __floats2half2_rn(c[mt][nt][0] + b0, c[mt][nt][1] + b1);
            *(__half2*)&Crow[(size_t)(row + 8) * KK + col] =
                __floats2half2_rn(c[mt][nt][2] + b0, c[mt][nt][3] + b1);
        }
    }
}

__constant__ int PT[10] = {0, 1, 1, 2, 2, 2, 3, 3, 3, 3};
__constant__ int PS[10] = {0, 0, 1, 0, 1, 2, 0, 1, 2, 3};

__global__ __launch_bounds__(128) void qkt_mma() {
    extern __shared__ __half smem[];
    const int tid = threadIdx.x, lane = tid & 31, wid = tid >> 5;
    const int wr = wid >> 1, wc = wid & 1;
    const int tT = PT[blockIdx.x], sT = PS[blockIdx.x], b = blockIdx.y;

    const __half* A = g_Qh + (size_t)b * TT * KK + (size_t)tT * 128 * KK;
    const __half* B = g_Kh + (size_t)b * TT * KK + (size_t)sT * 128 * KK;

    float c[4][8][4];
    zero_acc(c);
    gemm_mainloop<false>(smem, A, KK, B, KK, KK / BKH, tid, c, wr, wc, lane, wid);

    const float SCALE = 0.04419417382415922f;   // 1/sqrt(512)
    float* Crow = g_S + (size_t)b * TT * TT + (size_t)tT * 128 * TT;
    const int g = lane >> 2, q = lane & 3;
    #pragma unroll
    for (int mt = 0; mt < 4; ++mt) {
        #pragma unroll
        for (int nt = 0; nt < 8; ++nt) {
            const int row = wr * 64 + mt * 16 + g;
            const int col = sT * 128 + wc * 64 + nt * 8 + q * 2;
            *(float2*)&Crow[(size_t)row * TT + col] =
                make_float2(c[mt][nt][0] * SCALE, c[mt][nt][1] * SCALE);
            *(float2*)&Crow[(size_t)(row + 8) * TT + col] =
                make_float2(c[mt][nt][2] * SCALE, c[mt][nt][3] * SCALE);
        }
    }
}

__global__ __launch_bounds__(128) void av_mma(float* __restrict__ out) {
    extern __shared__ __half smem[];
    const int tid = threadIdx.x, lane = tid & 31, wid = tid >> 5;
    const int wr = wid >> 1, wc = wid & 1;
    const int vT = blockIdx.x, tT = 3 - blockIdx.y, b = blockIdx.z;  // heavy first

    const __half* A = g_Sh + (size_t)b * TT * TT + (size_t)tT * 128 * TT;
    const __half* B = g_Vh + (size_t)b * TT * VV + vT * 128;
    const int nc = (tT + 1) * (128 / BKH);     // causal K cutoff

    float c[4][8][4];
    zero_acc(c);
    gemm_mainloop<true>(smem, A, TT, B, VV, nc, tid, c, wr, wc, lane, wid);

    float* Crow = out + (size_t)b * TT * VV + (size_t)tT * 128 * VV;
    const int g = lane >> 2, q = lane & 3;
    #pragma unroll
    for (int mt = 0; mt < 4; ++mt) {
        #pragma unroll
        for (int nt = 0; nt < 8; ++nt) {
            const int row = wr * 64 + mt * 16 + g;
            const int col = vT * 128 + wc * 64 + nt * 8 + q * 2;
            *(float2*)&Crow[(size_t)row * VV + col] =
                make_float2(c[mt][nt][0], c[mt][nt][1]);
            *(float2*)&Crow[(size_t)(row + 8) * VV + col] =
                make_float2(c[mt][nt][2], c[mt][nt][3]);
        }
    }
}

// ---------------------------------------------------------------------------
// Aux kernels
// ---------------------------------------------------------------------------
__global__ __launch_bounds__(256) void convx_kernel(const float* __restrict__ x) {
    size_t i = ((size_t)blockIdx.x * 256 + threadIdx.x) * 4;
    float4 v = *(const float4*)(x + i);
    __half2* d = (__half2*)(g_xh + i);
    d[0] = __floats2half2_rn(v.x, v.y);
    d[1] = __floats2half2_rn(v.z, v.w);
}

__global__ __launch_bounds__(256) void convw_kernel(const float* __restrict__ Wq,
                                                    const float* __restrict__ Wk,
                                                    const float* __restrict__ Wv) {
    const int which = blockIdx.y;
    const float* W = (which == 0) ? Wq : ((which == 1) ? Wk : Wv);
    __half* D = g_Wh + (size_t)which * EE * KK;
    size_t i = ((size_t)blockIdx.x * 256 + threadIdx.x) * 4;
    float4 v = *(const float4*)(W + i);
    __half2* d = (__half2*)(D + i);
    d[0] = __floats2half2_rn(v.x, v.y);
    d[1] = __floats2half2_rn(v.z, v.w);
}

// Column softmax (axis = t), online max/sum. One thread per column s.
__global__ __launch_bounds__(128) void softmax_kernel() {
    const int b = blockIdx.y;
    const int s = blockIdx.x * 128 + threadIdx.x;
    const float* Sb = g_S + (size_t)b * TT * TT;
    __half* Sh = g_Sh + (size_t)b * TT * TT;
    const int tile0 = blockIdx.x * 128;
    const int w0 = tile0 + (threadIdx.x & ~31);

    float m = -1e30f, sum = 0.0f;
    #pragma unroll 2
    for (int t = w0; t < TT; ++t) {
        float xv = Sb[(size_t)t * TT + s];
        if (t >= s) {
            float nm = fmaxf(m, xv);
            sum = sum * __expf(m - nm) + __expf(xv - nm);
            m = nm;
        }
    }
    const float inv = 1.0f / sum;
    #pragma unroll 4
    for (int t = tile0; t < TT; ++t) {
        float r = 0.0f;
        if (t >= s) r = __expf(Sb[(size_t)t * TT + s] - m) * inv;
        Sh[(size_t)t * TT + s] = __float2half(r);
    }
}

// ---------------------------------------------------------------------------
extern "C" void kernel_launch(void* const* d_in, const int* in_sizes, int n_in,
                              void* d_out, int out_size) {
    const float* x  = (const float*)d_in[0];
    const float* Wq = (const float*)d_in[1];
    const float* bq = (const float*)d_in[2];
    const float* Wk = (const float*)d_in[3];
    const float* bk = (const float*)d_in[4];
    const float* Wv = (const float*)d_in[5];
    const float* bv = (const float*)d_in[6];
    float* out = (float*)d_out;

    cudaFuncSetAttribute(proj_mma, cudaFuncAttributeMaxDynamicSharedMemorySize, SMEM_BYTES);
    cudaFuncSetAttribute(qkt_mma,  cudaFuncAttributeMaxDynamicSharedMemorySize, SMEM_BYTES);
    cudaFuncSetAttribute(av_mma,   cudaFuncAttributeMaxDynamicSharedMemorySize, SMEM_BYTES);

    convx_kernel<<<(NB * TT * EE) / (256 * 4), 256>>>(x);
    convw_kernel<<<dim3((EE * KK) / (256 * 4), 3), 256>>>(Wq, Wk, Wv);
    proj_mma    <<<dim3(12, 256), 128, SMEM_BYTES>>>(bq, bk, bv);
    qkt_mma     <<<dim3(10, 64), 128, SMEM_BYTES>>>();
    softmax_kernel<<<dim3(4, 64), 128>>>();
    av_mma      <<<dim3(4, 4, 64), 128, SMEM_BYTES>>>(out);
}

// round 15
// speedup vs baseline: 1.2681x; 1.1411x over previous
#include <cuda_runtime.h>
#include <cuda_fp16.h>
#include <cstdint>
#include <math.h>

#define NB 64
#define TT 512
#define EE 512
#define KK 512
#define VV 512
#define BKH 64                  // K halves per chunk
#define SA  72                  // A / NT-B smem row stride (64 + 8 pad)
#define SBT 136                 // trans-B smem row stride (128 + 8 pad)

#define AHALVES (128 * SA)                  // 9216 halves
#define BHALVES (128 * SA)
#define STAGEH  (AHALVES + BHALVES)         // 18432 halves = 36864 B
#define SMEM_BYTES (2 * STAGEH * 2)         // 73728 B

// ---------------------------------------------------------------------------
// Device scratch
// ---------------------------------------------------------------------------
__device__ __half g_xh[(size_t)NB * TT * EE];
__device__ __half g_Wh[(size_t)3 * EE * KK];    // W natural [e][k] fp16
__device__ __half g_Qh[(size_t)NB * TT * KK];
__device__ __half g_Kh[(size_t)NB * TT * KK];
__device__ __half g_Vh[(size_t)NB * TT * VV];   // V natural [t][v] fp16
__device__ __half g_S [(size_t)NB * TT * TT];   // fp16 scores -> attn in place

// ---------------------------------------------------------------------------
// Helpers
// ---------------------------------------------------------------------------
__device__ __forceinline__ uint32_t smem_u32(const void* p) {
    uint32_t a;
    asm("{ .reg .u64 t; cvta.to.shared.u64 t, %1; cvt.u32.u64 %0, t; }"
        : "=r"(a) : "l"(p));
    return a;
}

#define CP_ASYNC16(dst, src) \
    asm volatile("cp.async.cg.shared.global [%0], [%1], 16;" \
                 :: "r"(dst), "l"(src) : "memory")
#define CP_COMMIT() asm volatile("cp.async.commit_group;" ::: "memory")
#define CP_WAIT0()  asm volatile("cp.async.wait_group 0;" ::: "memory")

#define LDSM_X4(r0, r1, r2, r3, addr)                                   \
    asm volatile("ldmatrix.sync.aligned.m8n8.x4.shared.b16 "            \
                 "{%0,%1,%2,%3}, [%4];"                                 \
                 : "=r"(r0), "=r"(r1), "=r"(r2), "=r"(r3) : "r"(addr))

#define LDSM_X4_T(r0, r1, r2, r3, addr)                                 \
    asm volatile("ldmatrix.sync.aligned.m8n8.x4.trans.shared.b16 "      \
                 "{%0,%1,%2,%3}, [%4];"                                 \
                 : "=r"(r0), "=r"(r1), "=r"(r2), "=r"(r3) : "r"(addr))

__device__ __forceinline__ void mma_f16(float* c, const uint32_t* a,
                                        const uint32_t* b) {
    asm volatile(
        "mma.sync.aligned.m16n8k16.row.col.f32.f16.f16.f32 "
        "{%0,%1,%2,%3}, {%4,%5,%6,%7}, {%8,%9}, {%0,%1,%2,%3};"
        : "+f"(c[0]), "+f"(c[1]), "+f"(c[2]), "+f"(c[3])
        : "r"(a[0]), "r"(a[1]), "r"(a[2]), "r"(a[3]), "r"(b[0]), "r"(b[1]));
}

// ---------------------------------------------------------------------------
// Tile loaders (cp.async 16B), 128-thread versions
// ---------------------------------------------------------------------------
// 128 rows x 64 halves (128 B/row = 8 chunks/row), stride SA
__device__ __forceinline__ void load_tile_k(__half* dst,
                                            const __half* __restrict__ gsrc,
                                            int ldh, int tid) {
    unsigned long long gb = (unsigned long long)__cvta_generic_to_global(gsrc);
    #pragma unroll
    for (int i = 0; i < 8; ++i) {
        int ch  = i * 128 + tid;           // 0..1023
        int row = ch >> 3;
        int off = ch & 7;
        uint32_t d = smem_u32(dst + row * SA + off * 8);
        unsigned long long s = gb + (unsigned long long)row * ((size_t)ldh * 2)
                                  + (unsigned)off * 16;
        CP_ASYNC16(d, s);
    }
}

// 64 rows x 128 halves (256 B/row = 16 chunks/row), stride SBT (trans B)
__device__ __forceinline__ void load_tile_t(__half* dst,
                                            const __half* __restrict__ gsrc,
                                            int ldh, int tid) {
    unsigned long long gb = (unsigned long long)__cvta_generic_to_global(gsrc);
    #pragma unroll
    for (int i = 0; i < 8; ++i) {
        int ch  = i * 128 + tid;           // 0..1023
        int row = ch >> 4;
        int off = ch & 15;
        uint32_t d = smem_u32(dst + row * SBT + off * 8);
        unsigned long long s = gb + (unsigned long long)row * ((size_t)ldh * 2)
                                  + (unsigned)off * 16;
        CP_ASYNC16(d, s);
    }
}

// ---------------------------------------------------------------------------
// One BKH=64 chunk for a 64x64 warp tile: 4 ks x (4 A-ldsm + 4 B-ldsm +
// 32 MMAs). ks staggered by warp parity.
// ---------------------------------------------------------------------------
template <bool TRB>
__device__ __forceinline__ void compute_chunk(const __half* As, const __half* Bs,
                                              float c[4][8][4],
                                              int wr, int wc, int lane, int wid) {
    const int arow  = lane & 15;
    const int asel  = (lane >> 4) * 8;
    const int bn    = (lane & 7) + ((lane >> 4) << 3);    // NT path
    const int bsel  = ((lane >> 3) & 1) * 8;
    const int tkrow = (lane & 7) + ((lane >> 3) & 1) * 8; // TR path
    const int tnoff = (lane >> 4) * 8;
    const int ks0   = (wid & 1) << 1;
    #pragma unroll
    for (int ksi = 0; ksi < 4; ++ksi) {
        const int ks = (ksi + ks0) & 3;
        const int kh = ks * 16;
        uint32_t a[4][4], b[8][2];
        #pragma unroll
        for (int mt = 0; mt < 4; ++mt) {
            uint32_t ad = smem_u32(As + (wr * 64 + mt * 16 + arow) * SA + kh + asel);
            LDSM_X4(a[mt][0], a[mt][1], a[mt][2], a[mt][3], ad);
        }
        #pragma unroll
        for (int np = 0; np < 4; ++np) {
            uint32_t r0, r1, r2, r3;
            if (!TRB) {
                uint32_t ad = smem_u32(Bs + (wc * 64 + np * 16 + bn) * SA + kh + bsel);
                LDSM_X4(r0, r1, r2, r3, ad);
            } else {
                uint32_t ad = smem_u32(Bs + (kh + tkrow) * SBT
                                          + wc * 64 + np * 16 + tnoff);
                LDSM_X4_T(r0, r1, r2, r3, ad);
            }
            b[np * 2][0] = r0;     b[np * 2][1] = r1;
            b[np * 2 + 1][0] = r2; b[np * 2 + 1][1] = r3;
        }
        #pragma unroll
        for (int mt = 0; mt < 4; ++mt)
            #pragma unroll
            for (int nt = 0; nt < 8; ++nt)
                mma_f16(c[mt][nt], a[mt], b[nt]);
    }
}

// Double-buffered mainloop: C[128x128] += A[128,K] . op(B), 128 threads
template <bool TRB>
__device__ __forceinline__ void gemm_mainloop(__half* smem,
                                              const __half* __restrict__ A, int lda,
                                              const __half* __restrict__ B, int ldb,
                                              int nc, int tid,
                                              float c[4][8][4],
                                              int wr, int wc, int lane, int wid) {
    __half* As0 = smem;
    __half* Bs0 = smem + AHALVES;
    __half* As1 = smem + STAGEH;
    __half* Bs1 = smem + STAGEH + AHALVES;

    load_tile_k(As0, A, lda, tid);
    if (TRB) load_tile_t(Bs0, B, ldb, tid);
    else     load_tile_k(Bs0, B, ldb, tid);
    CP_COMMIT();

    for (int ch = 0; ch < nc; ++ch) {
        const int buf = ch & 1;
        CP_WAIT0();
        __syncthreads();
        if (ch + 1 < nc) {
            __half* An = buf ? As0 : As1;
            __half* Bn = buf ? Bs0 : Bs1;
            load_tile_k(An, A + (size_t)(ch + 1) * BKH, lda, tid);
            if (TRB) load_tile_t(Bn, B + (size_t)(ch + 1) * BKH * ldb, ldb, tid);
            else     load_tile_k(Bn, B + (size_t)(ch + 1) * BKH, ldb, tid);
            CP_COMMIT();
        }
        compute_chunk<TRB>(buf ? As1 : As0, (buf ? As1 : As0) + AHALVES,
                           c, wr, wc, lane, wid);
    }
}

__device__ __forceinline__ void zero_acc(float c[4][8][4]) {
    #pragma unroll
    for (int i = 0; i < 4; ++i)
        #pragma unroll
        for (int j = 0; j < 8; ++j)
            #pragma unroll
            for (int k = 0; k < 4; ++k) c[i][j][k] = 0.0f;
}

// ---------------------------------------------------------------------------
// GEMM kernels: 128 threads = 4 warps (wr 0..1, wc 0..1), warp tile 64x64,
// CTA tile 128x128.
// ---------------------------------------------------------------------------
__global__ __launch_bounds__(128) void proj_mma(const float* __restrict__ bq,
                                                const float* __restrict__ bk,
                                                const float* __restrict__ bv) {
    extern __shared__ __half smem[];
    const int tid = threadIdx.x, lane = tid & 31, wid = tid >> 5;
    const int wr = wid >> 1, wc = wid & 1;
    const int which = blockIdx.x >> 2, colT = blockIdx.x & 3;
    const int rowT = blockIdx.y;

    const __half* A = g_xh + (size_t)rowT * 128 * EE;
    const __half* B = g_Wh + (size_t)which * EE * KK + colT * 128;
    __half* Cmat = (which == 0) ? g_Qh : ((which == 1) ? g_Kh : g_Vh);
    const float* bias = (which == 0) ? bq : ((which == 1) ? bk : bv);

    float c[4][8][4];
    zero_acc(c);
    gemm_mainloop<true>(smem, A, EE, B, KK, EE / BKH, tid, c, wr, wc, lane, wid);

    __half* Crow = Cmat + (size_t)rowT * 128 * KK;
    const int g = lane >> 2, q = lane & 3;
    #pragma unroll
    for (int mt = 0; mt < 4; ++mt) {
        #pragma unroll
        for (int nt = 0; nt < 8; ++nt) {
            const int row = wr * 64 + mt * 16 + g;
            const int col = colT * 128 + wc * 64 + nt * 8 + q * 2;
            float b0 = __ldg(bias + col), b1 = __ldg(bias + col + 1);
            *(__half2*)&Crow[(size_t)row * KK + col] =
                __floats2half2_rn(c[mt][nt][0] + b0, c[mt][nt][1] + b1);
            *(__half2*)&Crow[(size_t)(row + 8) * KK + col] =
                __floats2half2_rn(c[mt][nt][2] + b0, c[mt][nt][3] + b1);
        }
    }
}

__constant__ int PT[10] = {0, 1, 1, 2, 2, 2, 3, 3, 3, 3};
__constant__ int PS[10] = {0, 0, 1, 0, 1, 2, 0, 1, 2, 3};

// Scores: S = scale * Q K^T, written fp16 into g_S (lower-triangular tiles)
__global__ __launch_bounds__(128) void qkt_mma() {
    extern __shared__ __half smem[];
    const int tid = threadIdx.x, lane = tid & 31, wid = tid >> 5;
    const int wr = wid >> 1, wc = wid & 1;
    const int tT = PT[blockIdx.x], sT = PS[blockIdx.x], b = blockIdx.y;

    const __half* A = g_Qh + (size_t)b * TT * KK + (size_t)tT * 128 * KK;
    const __half* B = g_Kh + (size_t)b * TT * KK + (size_t)sT * 128 * KK;

    float c[4][8][4];
    zero_acc(c);
    gemm_mainloop<false>(smem, A, KK, B, KK, KK / BKH, tid, c, wr, wc, lane, wid);

    const float SCALE = 0.04419417382415922f;   // 1/sqrt(512)
    __half* Crow = g_S + (size_t)b * TT * TT + (size_t)tT * 128 * TT;
    const int g = lane >> 2, q = lane & 3;
    #pragma unroll
    for (int mt = 0; mt < 4; ++mt) {
        #pragma unroll
        for (int nt = 0; nt < 8; ++nt) {
            const int row = wr * 64 + mt * 16 + g;
            const int col = sT * 128 + wc * 64 + nt * 8 + q * 2;
            *(__half2*)&Crow[(size_t)row * TT + col] =
                __floats2half2_rn(c[mt][nt][0] * SCALE, c[mt][nt][1] * SCALE);
            *(__half2*)&Crow[(size_t)(row + 8) * TT + col] =
                __floats2half2_rn(c[mt][nt][2] * SCALE, c[mt][nt][3] * SCALE);
        }
    }
}

__global__ __launch_bounds__(128) void av_mma(float* __restrict__ out) {
    extern __shared__ __half smem[];
    const int tid = threadIdx.x, lane = tid & 31, wid = tid >> 5;
    const int wr = wid >> 1, wc = wid & 1;
    const int vT = blockIdx.x, tT = 3 - blockIdx.y, b = blockIdx.z;  // heavy first

    const __half* A = g_S  + (size_t)b * TT * TT + (size_t)tT * 128 * TT;
    const __half* B = g_Vh + (size_t)b * TT * VV + vT * 128;
    const int nc = (tT + 1) * (128 / BKH);     // causal K cutoff

    float c[4][8][4];
    zero_acc(c);
    gemm_mainloop<true>(smem, A, TT, B, VV, nc, tid, c, wr, wc, lane, wid);

    float* Crow = out + (size_t)b * TT * VV + (size_t)tT * 128 * VV;
    const int g = lane >> 2, q = lane & 3;
    #pragma unroll
    for (int mt = 0; mt < 4; ++mt) {
        #pragma unroll
        for (int nt = 0; nt < 8; ++nt) {
            const int row = wr * 64 + mt * 16 + g;
            const int col = vT * 128 + wc * 64 + nt * 8 + q * 2;
            *(float2*)&Crow[(size_t)row * VV + col] =
                make_float2(c[mt][nt][0], c[mt][nt][1]);
            *(float2*)&Crow[(size_t)(row + 8) * VV + col] =
                make_float2(c[mt][nt][2], c[mt][nt][3]);
        }
    }
}

// ---------------------------------------------------------------------------
// Aux kernels
// ---------------------------------------------------------------------------
__global__ __launch_bounds__(256) void convx_kernel(const float* __restrict__ x) {
    size_t i = ((size_t)blockIdx.x * 256 + threadIdx.x) * 4;
    float4 v = *(const float4*)(x + i);
    __half2* d = (__half2*)(g_xh + i);
    d[0] = __floats2half2_rn(v.x, v.y);
    d[1] = __floats2half2_rn(v.z, v.w);
}

__global__ __launch_bounds__(256) void convw_kernel(const float* __restrict__ Wq,
                                                    const float* __restrict__ Wk,
                                                    const float* __restrict__ Wv) {
    const int which = blockIdx.y;
    const float* W = (which == 0) ? Wq : ((which == 1) ? Wk : Wv);
    __half* D = g_Wh + (size_t)which * EE * KK;
    size_t i = ((size_t)blockIdx.x * 256 + threadIdx.x) * 4;
    float4 v = *(const float4*)(W + i);
    __half2* d = (__half2*)(D + i);
    d[0] = __floats2half2_rn(v.x, v.y);
    d[1] = __floats2half2_rn(v.z, v.w);
}

// Column softmax (axis = t), online max/sum, fp16 in-place on g_S.
// One thread per column s; fp32 math.
__global__ __launch_bounds__(128) void softmax_kernel() {
    const int b = blockIdx.y;
    const int s = blockIdx.x * 128 + threadIdx.x;
    __half* Sb = g_S + (size_t)b * TT * TT;
    const int tile0 = blockIdx.x * 128;
    const int w0 = tile0 + (threadIdx.x & ~31);

    float m = -1e30f, sum = 0.0f;
    #pragma unroll 2
    for (int t = w0; t < TT; ++t) {
        float xv = __half2float(Sb[(size_t)t * TT + s]);
        if (t >= s) {
            float nm = fmaxf(m, xv);
            sum = sum * __expf(m - nm) + __expf(xv - nm);
            m = nm;
        }
    }
    const float inv = 1.0f / sum;
    #pragma unroll 4
    for (int t = tile0; t < TT; ++t) {
        float r = 0.0f;
        if (t >= s)
            r = __expf(__half2float(Sb[(size_t)t * TT + s]) - m) * inv;
        Sb[(size_t)t * TT + s] = __float2half(r);
    }
}

// ---------------------------------------------------------------------------
extern "C" void kernel_launch(void* const* d_in, const int* in_sizes, int n_in,
                              void* d_out, int out_size) {
    const float* x  = (const float*)d_in[0];
    const float* Wq = (const float*)d_in[1];
    const float* bq = (const float*)d_in[2];
    const float* Wk = (const float*)d_in[3];
    const float* bk = (const float*)d_in[4];
    const float* Wv = (const float*)d_in[5];
    const float* bv = (const float*)d_in[6];
    float* out = (float*)d_out;

    cudaFuncSetAttribute(proj_mma, cudaFuncAttributeMaxDynamicSharedMemorySize, SMEM_BYTES);
    cudaFuncSetAttribute(qkt_mma,  cudaFuncAttributeMaxDynamicSharedMemorySize, SMEM_BYTES);
    cudaFuncSetAttribute(av_mma,   cudaFuncAttributeMaxDynamicSharedMemorySize, SMEM_BYTES);

    convx_kernel<<<(NB * TT * EE) / (256 * 4), 256>>>(x);
    convw_kernel<<<dim3((EE * KK) / (256 * 4), 3), 256>>>(Wq, Wk, Wv);
    proj_mma    <<<dim3(12, 256), 128, SMEM_BYTES>>>(bq, bk, bv);
    qkt_mma     <<<dim3(10, 64), 128, SMEM_BYTES>>>();
    softmax_kernel<<<dim3(4, 64), 128>>>();
    av_mma      <<<dim3(4, 4, 64), 128, SMEM_BYTES>>>(out);
}

// round 16
// speedup vs baseline: 1.6795x; 1.3244x over previous
#include <cuda_runtime.h>
#include <cuda_fp16.h>
#include <cstdint>
#include <math.h>

#define NB 64
#define TT 512
#define EE 512
#define KK 512
#define VV 512
#define BKH 64                  // K halves per chunk
#define SA  72                  // A / NT-B smem row stride (64 + 8 pad)
#define SBT 136                 // trans-B smem row stride (128 + 8 pad)

#define AHALVES (128 * SA)                  // 9216 halves
#define BHALVES (128 * SA)
#define STAGEH  (AHALVES + BHALVES)         // 18432 halves = 36864 B
#define SMEM_BYTES (2 * STAGEH * 2)         // 73728 B

// ---------------------------------------------------------------------------
// Device scratch
// ---------------------------------------------------------------------------
__device__ __half g_xh[(size_t)NB * TT * EE];
__device__ __half g_Wh[(size_t)3 * EE * KK];    // W natural [e][k] fp16
__device__ __half g_Qh[(size_t)NB * TT * KK];
__device__ __half g_Kh[(size_t)NB * TT * KK];
__device__ __half g_Vh[(size_t)NB * TT * VV];   // V natural [t][v] fp16
__device__ __half g_S [(size_t)NB * TT * TT];   // E = exp(scale*S), causal-zeroed
__device__ __half g_Dr[(size_t)NB * TT];        // 1/colsum per (b, s)

// ---------------------------------------------------------------------------
// Helpers
// ---------------------------------------------------------------------------
__device__ __forceinline__ uint32_t smem_u32(const void* p) {
    uint32_t a;
    asm("{ .reg .u64 t; cvta.to.shared.u64 t, %1; cvt.u32.u64 %0, t; }"
        : "=r"(a) : "l"(p));
    return a;
}

#define CP_ASYNC16(dst, src) \
    asm volatile("cp.async.cg.shared.global [%0], [%1], 16;" \
                 :: "r"(dst), "l"(src) : "memory")
#define CP_COMMIT() asm volatile("cp.async.commit_group;" ::: "memory")
#define CP_WAIT0()  asm volatile("cp.async.wait_group 0;" ::: "memory")

#define LDSM_X4(r0, r1, r2, r3, addr)                                   \
    asm volatile("ldmatrix.sync.aligned.m8n8.x4.shared.b16 "            \
                 "{%0,%1,%2,%3}, [%4];"                                 \
                 : "=r"(r0), "=r"(r1), "=r"(r2), "=r"(r3) : "r"(addr))

#define LDSM_X4_T(r0, r1, r2, r3, addr)                                 \
    asm volatile("ldmatrix.sync.aligned.m8n8.x4.trans.shared.b16 "      \
                 "{%0,%1,%2,%3}, [%4];"                                 \
                 : "=r"(r0), "=r"(r1), "=r"(r2), "=r"(r3) : "r"(addr))

__device__ __forceinline__ void mma_f16(float* c, const uint32_t* a,
                                        const uint32_t* b) {
    asm volatile(
        "mma.sync.aligned.m16n8k16.row.col.f32.f16.f16.f32 "
        "{%0,%1,%2,%3}, {%4,%5,%6,%7}, {%8,%9}, {%0,%1,%2,%3};"
        : "+f"(c[0]), "+f"(c[1]), "+f"(c[2]), "+f"(c[3])
        : "r"(a[0]), "r"(a[1]), "r"(a[2]), "r"(a[3]), "r"(b[0]), "r"(b[1]));
}

__device__ __forceinline__ uint32_t hmul2_u32(uint32_t a, __half2 s) {
    __half2 h = __hmul2(*(__half2*)&a, s);
    return *(uint32_t*)&h;
}

// ---------------------------------------------------------------------------
// Tile loaders (cp.async 16B), 128-thread versions
// ---------------------------------------------------------------------------
// 128 rows x 64 halves (128 B/row = 8 chunks/row), stride SA
__device__ __forceinline__ void load_tile_k(__half* dst,
                                            const __half* __restrict__ gsrc,
                                            int ldh, int tid) {
    unsigned long long gb = (unsigned long long)__cvta_generic_to_global(gsrc);
    #pragma unroll
    for (int i = 0; i < 8; ++i) {
        int ch  = i * 128 + tid;           // 0..1023
        int row = ch >> 3;
        int off = ch & 7;
        uint32_t d = smem_u32(dst + row * SA + off * 8);
        unsigned long long s = gb + (unsigned long long)row * ((size_t)ldh * 2)
                                  + (unsigned)off * 16;
        CP_ASYNC16(d, s);
    }
}

// 64 rows x 128 halves (256 B/row = 16 chunks/row), stride SBT (trans B)
__device__ __forceinline__ void load_tile_t(__half* dst,
                                            const __half* __restrict__ gsrc,
                                            int ldh, int tid) {
    unsigned long long gb = (unsigned long long)__cvta_generic_to_global(gsrc);
    #pragma unroll
    for (int i = 0; i < 8; ++i) {
        int ch  = i * 128 + tid;           // 0..1023
        int row = ch >> 4;
        int off = ch & 15;
        uint32_t d = smem_u32(dst + row * SBT + off * 8);
        unsigned long long s = gb + (unsigned long long)row * ((size_t)ldh * 2)
                                  + (unsigned)off * 16;
        CP_ASYNC16(d, s);
    }
}

// ---------------------------------------------------------------------------
// One BKH=64 chunk for a 64x64 warp tile: 4 ks x (4 A-ldsm + 4 B-ldsm +
// 32 MMAs). ks staggered by warp parity. SCA: scale A fragments by per-k
// (column s) reciprocal-denominator pairs from ds (32 half2 per chunk).
// ---------------------------------------------------------------------------
template <bool TRB, bool SCA>
__device__ __forceinline__ void compute_chunk(const __half* As, const __half* Bs,
                                              const __half2* __restrict__ ds,
                                              float c[4][8][4],
                                              int wr, int wc, int lane, int wid) {
    const int arow  = lane & 15;
    const int asel  = (lane >> 4) * 8;
    const int bn    = (lane & 7) + ((lane >> 4) << 3);    // NT path
    const int bsel  = ((lane >> 3) & 1) * 8;
    const int tkrow = (lane & 7) + ((lane >> 3) & 1) * 8; // TR path
    const int tnoff = (lane >> 4) * 8;
    const int ks0   = (wid & 1) << 1;
    const int dq    = lane & 3;
    #pragma unroll
    for (int ksi = 0; ksi < 4; ++ksi) {
        const int ks = (ksi + ks0) & 3;
        const int kh = ks * 16;
        uint32_t a[4][4], b[8][2];
        #pragma unroll
        for (int mt = 0; mt < 4; ++mt) {
            uint32_t ad = smem_u32(As + (wr * 64 + mt * 16 + arow) * SA + kh + asel);
            LDSM_X4(a[mt][0], a[mt][1], a[mt][2], a[mt][3], ad);
        }
        if (SCA) {
            // A frag k-pairs: regs 0,1 at k = kh + 2*(lane&3); regs 2,3 at +8
            __half2 d0 = __ldg(ds + ks * 8 + dq);
            __half2 d1 = __ldg(ds + ks * 8 + 4 + dq);
            #pragma unroll
            for (int mt = 0; mt < 4; ++mt) {
                a[mt][0] = hmul2_u32(a[mt][0], d0);
                a[mt][1] = hmul2_u32(a[mt][1], d0);
                a[mt][2] = hmul2_u32(a[mt][2], d1);
                a[mt][3] = hmul2_u32(a[mt][3], d1);
            }
        }
        #pragma unroll
        for (int np = 0; np < 4; ++np) {
            uint32_t r0, r1, r2, r3;
            if (!TRB) {
                uint32_t ad = smem_u32(Bs + (wc * 64 + np * 16 + bn) * SA + kh + bsel);
                LDSM_X4(r0, r1, r2, r3, ad);
            } else {
                uint32_t ad = smem_u32(Bs + (kh + tkrow) * SBT
                                          + wc * 64 + np * 16 + tnoff);
                LDSM_X4_T(r0, r1, r2, r3, ad);
            }
            b[np * 2][0] = r0;     b[np * 2][1] = r1;
            b[np * 2 + 1][0] = r2; b[np * 2 + 1][1] = r3;
        }
        #pragma unroll
        for (int mt = 0; mt < 4; ++mt)
            #pragma unroll
            for (int nt = 0; nt < 8; ++nt)
                mma_f16(c[mt][nt], a[mt], b[nt]);
    }
}

// Double-buffered mainloop: C[128x128] += A[128,K] . op(B), 128 threads
template <bool TRB, bool SCA>
__device__ __forceinline__ void gemm_mainloop(__half* smem,
                                              const __half* __restrict__ A, int lda,
                                              const __half* __restrict__ B, int ldb,
                                              const __half2* __restrict__ ds,
                                              int nc, int tid,
                                              float c[4][8][4],
                                              int wr, int wc, int lane, int wid) {
    __half* As0 = smem;
    __half* Bs0 = smem + AHALVES;
    __half* As1 = smem + STAGEH;
    __half* Bs1 = smem + STAGEH + AHALVES;

    load_tile_k(As0, A, lda, tid);
    if (TRB) load_tile_t(Bs0, B, ldb, tid);
    else     load_tile_k(Bs0, B, ldb, tid);
    CP_COMMIT();

    for (int ch = 0; ch < nc; ++ch) {
        const int buf = ch & 1;
        CP_WAIT0();
        __syncthreads();
        if (ch + 1 < nc) {
            __half* An = buf ? As0 : As1;
            __half* Bn = buf ? Bs0 : Bs1;
            load_tile_k(An, A + (size_t)(ch + 1) * BKH, lda, tid);
            if (TRB) load_tile_t(Bn, B + (size_t)(ch + 1) * BKH * ldb, ldb, tid);
            else     load_tile_k(Bn, B + (size_t)(ch + 1) * BKH, ldb, tid);
            CP_COMMIT();
        }
        compute_chunk<TRB, SCA>(buf ? As1 : As0, (buf ? As1 : As0) + AHALVES,
                                SCA ? ds + ch * 32 : (const __half2*)nullptr,
                                c, wr, wc, lane, wid);
    }
}

__device__ __forceinline__ void zero_acc(float c[4][8][4]) {
    #pragma unroll
    for (int i = 0; i < 4; ++i)
        #pragma unroll
        for (int j = 0; j < 8; ++j)
            #pragma unroll
            for (int k = 0; k < 4; ++k) c[i][j][k] = 0.0f;
}

// ---------------------------------------------------------------------------
// GEMM kernels: 128 threads = 4 warps (wr 0..1, wc 0..1), warp tile 64x64,
// CTA tile 128x128.
// ---------------------------------------------------------------------------
__global__ __launch_bounds__(128) void proj_mma(const float* __restrict__ bq,
                                                const float* __restrict__ bk,
                                                const float* __restrict__ bv) {
    extern __shared__ __half smem[];
    const int tid = threadIdx.x, lane = tid & 31, wid = tid >> 5;
    const int wr = wid >> 1, wc = wid & 1;
    const int which = blockIdx.x >> 2, colT = blockIdx.x & 3;
    const int rowT = blockIdx.y;

    const __half* A = g_xh + (size_t)rowT * 128 * EE;
    const __half* B = g_Wh + (size_t)which * EE * KK + colT * 128;
    __half* Cmat = (which == 0) ? g_Qh : ((which == 1) ? g_Kh : g_Vh);
    const float* bias = (which == 0) ? bq : ((which == 1) ? bk : bv);

    float c[4][8][4];
    zero_acc(c);
    gemm_mainloop<true, false>(smem, A, EE, B, KK, nullptr, EE / BKH, tid,
                               c, wr, wc, lane, wid);

    __half* Crow = Cmat + (size_t)rowT * 128 * KK;
    const int g = lane >> 2, q = lane & 3;
    #pragma unroll
    for (int mt = 0; mt < 4; ++mt) {
        #pragma unroll
        for (int nt = 0; nt < 8; ++nt) {
            const int row = wr * 64 + mt * 16 + g;
            const int col = colT * 128 + wc * 64 + nt * 8 + q * 2;
            float b0 = __ldg(bias + col), b1 = __ldg(bias + col + 1);
            *(__half2*)&Crow[(size_t)row * KK + col] =
                __floats2half2_rn(c[mt][nt][0] + b0, c[mt][nt][1] + b1);
            *(__half2*)&Crow[(size_t)(row + 8) * KK + col] =
                __floats2half2_rn(c[mt][nt][2] + b0, c[mt][nt][3] + b1);
        }
    }
}

__constant__ int PT[10] = {0, 1, 1, 2, 2, 2, 3, 3, 3, 3};
__constant__ int PS[10] = {0, 0, 1, 0, 1, 2, 0, 1, 2, 3};

// Scores: E = exp(scale * Q K^T), causal-zeroed, fp16 into g_S
__global__ __launch_bounds__(128) void qkt_mma() {
    extern __shared__ __half smem[];
    const int tid = threadIdx.x, lane = tid & 31, wid = tid >> 5;
    const int wr = wid >> 1, wc = wid & 1;
    const int tT = PT[blockIdx.x], sT = PS[blockIdx.x], b = blockIdx.y;

    const __half* A = g_Qh + (size_t)b * TT * KK + (size_t)tT * 128 * KK;
    const __half* B = g_Kh + (size_t)b * TT * KK + (size_t)sT * 128 * KK;

    float c[4][8][4];
    zero_acc(c);
    gemm_mainloop<false, false>(smem, A, KK, B, KK, nullptr, KK / BKH, tid,
                                c, wr, wc, lane, wid);

    const float SCALE = 0.04419417382415922f;   // 1/sqrt(512)
    __half* Crow = g_S + (size_t)b * TT * TT + (size_t)tT * 128 * TT;
    const int g = lane >> 2, q = lane & 3;
    #pragma unroll
    for (int mt = 0; mt < 4; ++mt) {
        #pragma unroll
        for (int nt = 0; nt < 8; ++nt) {
            const int row = wr * 64 + mt * 16 + g;
            const int col = wc * 64 + nt * 8 + q * 2;
            const int tg0 = tT * 128 + row, tg1 = tg0 + 8;
            const int sg0 = sT * 128 + col, sg1 = sg0 + 1;
            float e00 = (tg0 >= sg0) ? __expf(c[mt][nt][0] * SCALE) : 0.0f;
            float e01 = (tg0 >= sg1) ? __expf(c[mt][nt][1] * SCALE) : 0.0f;
            float e10 = (tg1 >= sg0) ? __expf(c[mt][nt][2] * SCALE) : 0.0f;
            float e11 = (tg1 >= sg1) ? __expf(c[mt][nt][3] * SCALE) : 0.0f;
            *(__half2*)&Crow[(size_t)row * TT + sT * 128 + col] =
                __floats2half2_rn(e00, e01);
            *(__half2*)&Crow[(size_t)(row + 8) * TT + sT * 128 + col] =
                __floats2half2_rn(e10, e11);
        }
    }
}

// Column reciprocal denominator: g_Dr[b][s] = 1 / sum_t E[t][s]
__global__ __launch_bounds__(128) void colsum_kernel() {
    const int b = blockIdx.y;
    const int s = blockIdx.x * 128 + threadIdx.x;
    const __half* Sb = g_S + (size_t)b * TT * TT;
    const int w0 = blockIdx.x * 128 + (threadIdx.x & ~31);

    float sum = 0.0f;
    #pragma unroll 4
    for (int t = w0; t < TT; ++t)
        sum += __half2float(Sb[(size_t)t * TT + s]);
    g_Dr[(size_t)b * TT + s] = __float2half(1.0f / sum);
}

// Output: out = (E . diag(1/D)) @ V, causal K cutoff, A-frags scaled in regs
__global__ __launch_bounds__(128) void av_mma(float* __restrict__ out) {
    extern __shared__ __half smem[];
    const int tid = threadIdx.x, lane = tid & 31, wid = tid >> 5;
    const int wr = wid >> 1, wc = wid & 1;
    const int vT = blockIdx.x, tT = 3 - blockIdx.y, b = blockIdx.z;  // heavy first

    const __half* A = g_S  + (size_t)b * TT * TT + (size_t)tT * 128 * TT;
    const __half* B = g_Vh + (size_t)b * TT * VV + vT * 128;
    const __half2* ds = (const __half2*)(g_Dr + (size_t)b * TT);
    const int nc = (tT + 1) * (128 / BKH);     // causal K cutoff

    float c[4][8][4];
    zero_acc(c);
    gemm_mainloop<true, true>(smem, A, TT, B, VV, ds, nc, tid,
                              c, wr, wc, lane, wid);

    float* Crow = out + (size_t)b * TT * VV + (size_t)tT * 128 * VV;
    const int g = lane >> 2, q = lane & 3;
    #pragma unroll
    for (int mt = 0; mt < 4; ++mt) {
        #pragma unroll
        for (int nt = 0; nt < 8; ++nt) {
            const int row = wr * 64 + mt * 16 + g;
            const int col = vT * 128 + wc * 64 + nt * 8 + q * 2;
            *(float2*)&Crow[(size_t)row * VV + col] =
                make_float2(c[mt][nt][0], c[mt][nt][1]);
            *(float2*)&Crow[(size_t)(row + 8) * VV + col] =
                make_float2(c[mt][nt][2], c[mt][nt][3]);
        }
    }
}

// ---------------------------------------------------------------------------
// Aux kernels
// ---------------------------------------------------------------------------
__global__ __launch_bounds__(256) void convx_kernel(const float* __restrict__ x) {
    size_t i = ((size_t)blockIdx.x * 256 + threadIdx.x) * 4;
    float4 v = *(const float4*)(x + i);
    __half2* d = (__half2*)(g_xh + i);
    d[0] = __floats2half2_rn(v.x, v.y);
    d[1] = __floats2half2_rn(v.z, v.w);
}

__global__ __launch_bounds__(256) void convw_kernel(const float* __restrict__ Wq,
                                                    const float* __restrict__ Wk,
                                                    const float* __restrict__ Wv) {
    const int which = blockIdx.y;
    const float* W = (which == 0) ? Wq : ((which == 1) ? Wk : Wv);
    __half* D = g_Wh + (size_t)which * EE * KK;
    size_t i = ((size_t)blockIdx.x * 256 + threadIdx.x) * 4;
    float4 v = *(const float4*)(W + i);
    __half2* d = (__half2*)(D + i);
    d[0] = __floats2half2_rn(v.x, v.y);
    d[1] = __floats2half2_rn(v.z, v.w);
}

// ---------------------------------------------------------------------------
extern "C" void kernel_launch(void* const* d_in, const int* in_sizes, int n_in,
                              void* d_out, int out_size) {
    const float* x  = (const float*)d_in[0];
    const float* Wq = (const float*)d_in[1];
    const float* bq = (const float*)d_in[2];
    const float* Wk = (const float*)d_in[3];
    const float* bk = (const float*)d_in[4];
    const float* Wv = (const float*)d_in[5];
    const float* bv = (const float*)d_in[6];
    float* out = (float*)d_out;

    cudaFuncSetAttribute(proj_mma, cudaFuncAttributeMaxDynamicSharedMemorySize, SMEM_BYTES);
    cudaFuncSetAttribute(qkt_mma,  cudaFuncAttributeMaxDynamicSharedMemorySize, SMEM_BYTES);
    cudaFuncSetAttribute(av_mma,   cudaFuncAttributeMaxDynamicSharedMemorySize, SMEM_BYTES);

    convx_kernel <<<(NB * TT * EE) / (256 * 4), 256>>>(x);
    convw_kernel <<<dim3((EE * KK) / (256 * 4), 3), 256>>>(Wq, Wk, Wv);
    proj_mma     <<<dim3(12, 256), 128, SMEM_BYTES>>>(bq, bk, bv);
    qkt_mma      <<<dim3(10, 64), 128, SMEM_BYTES>>>();
    colsum_kernel<<<dim3(4, 64), 128>>>();
    av_mma       <<<dim3(4, 4, 64), 128, SMEM_BYTES>>>(out);
}

// round 17
// speedup vs baseline: 1.7804x; 1.0601x over previous
#include <cuda_runtime.h>
#include <cuda_fp16.h>
#include <cstdint>
#include <math.h>

#define NB 64
#define TT 512
#define EE 512
#define KK 512
#define VV 512
#define BKH 64                  // K halves per chunk
#define SA  72                  // A / NT-B smem row stride (64 + 8 pad)
#define SBT 136                 // trans-B smem row stride (128 + 8 pad)

#define AHALVES (128 * SA)                  // 9216 halves
#define BHALVES (128 * SA)
#define STAGEH  (AHALVES + BHALVES)         // 18432 halves = 36864 B
#define SMEM_BYTES (2 * STAGEH * 2)         // 73728 B

// ---------------------------------------------------------------------------
// Device scratch
// ---------------------------------------------------------------------------
__device__ __half g_xh[(size_t)NB * TT * EE];
__device__ __half g_Wh[(size_t)3 * EE * KK];    // W natural [e][k] fp16
__device__ __half g_Qh[(size_t)NB * TT * KK];
__device__ __half g_Kh[(size_t)NB * TT * KK];
__device__ __half g_Vh[(size_t)NB * TT * VV];   // V natural [t][v] fp16
__device__ __half g_S [(size_t)NB * TT * TT];   // E = exp(scale*S), causal-zeroed
__device__ float  g_D [(size_t)NB * TT];        // colsum accumulators (fp32)
__device__ __half g_Dr[(size_t)NB * TT];        // 1/colsum per (b, s)

// ---------------------------------------------------------------------------
// Helpers
// ---------------------------------------------------------------------------
__device__ __forceinline__ uint32_t smem_u32(const void* p) {
    uint32_t a;
    asm("{ .reg .u64 t; cvta.to.shared.u64 t, %1; cvt.u32.u64 %0, t; }"
        : "=r"(a) : "l"(p));
    return a;
}

#define CP_ASYNC16(dst, src) \
    asm volatile("cp.async.cg.shared.global [%0], [%1], 16;" \
                 :: "r"(dst), "l"(src) : "memory")
#define CP_COMMIT() asm volatile("cp.async.commit_group;" ::: "memory")
#define CP_WAIT0()  asm volatile("cp.async.wait_group 0;" ::: "memory")

#define LDSM_X4(r0, r1, r2, r3, addr)                                   \
    asm volatile("ldmatrix.sync.aligned.m8n8.x4.shared.b16 "            \
                 "{%0,%1,%2,%3}, [%4];"                                 \
                 : "=r"(r0), "=r"(r1), "=r"(r2), "=r"(r3) : "r"(addr))

#define LDSM_X4_T(r0, r1, r2, r3, addr)                                 \
    asm volatile("ldmatrix.sync.aligned.m8n8.x4.trans.shared.b16 "      \
                 "{%0,%1,%2,%3}, [%4];"                                 \
                 : "=r"(r0), "=r"(r1), "=r"(r2), "=r"(r3) : "r"(addr))

__device__ __forceinline__ void mma_f16(float* c, const uint32_t* a,
                                        const uint32_t* b) {
    asm volatile(
        "mma.sync.aligned.m16n8k16.row.col.f32.f16.f16.f32 "
        "{%0,%1,%2,%3}, {%4,%5,%6,%7}, {%8,%9}, {%0,%1,%2,%3};"
        : "+f"(c[0]), "+f"(c[1]), "+f"(c[2]), "+f"(c[3])
        : "r"(a[0]), "r"(a[1]), "r"(a[2]), "r"(a[3]), "r"(b[0]), "r"(b[1]));
}

__device__ __forceinline__ uint32_t hmul2_u32(uint32_t a, __half2 s) {
    __half2 h = __hmul2(*(__half2*)&a, s);
    return *(uint32_t*)&h;
}

// ---------------------------------------------------------------------------
// Tile loaders (cp.async 16B), 128-thread versions
// ---------------------------------------------------------------------------
__device__ __forceinline__ void load_tile_k(__half* dst,
                                            const __half* __restrict__ gsrc,
                                            int ldh, int tid) {
    unsigned long long gb = (unsigned long long)__cvta_generic_to_global(gsrc);
    #pragma unroll
    for (int i = 0; i < 8; ++i) {
        int ch  = i * 128 + tid;           // 0..1023
        int row = ch >> 3;
        int off = ch & 7;
        uint32_t d = smem_u32(dst + row * SA + off * 8);
        unsigned long long s = gb + (unsigned long long)row * ((size_t)ldh * 2)
                                  + (unsigned)off * 16;
        CP_ASYNC16(d, s);
    }
}

__device__ __forceinline__ void load_tile_t(__half* dst,
                                            const __half* __restrict__ gsrc,
                                            int ldh, int tid) {
    unsigned long long gb = (unsigned long long)__cvta_generic_to_global(gsrc);
    #pragma unroll
    for (int i = 0; i < 8; ++i) {
        int ch  = i * 128 + tid;           // 0..1023
        int row = ch >> 4;
        int off = ch & 15;
        uint32_t d = smem_u32(dst + row * SBT + off * 8);
        unsigned long long s = gb + (unsigned long long)row * ((size_t)ldh * 2)
                                  + (unsigned)off * 16;
        CP_ASYNC16(d, s);
    }
}

// ---------------------------------------------------------------------------
// One BKH=64 chunk for a 64x64 warp tile: 4 ks x (4 A-ldsm + 4 B-ldsm +
// 32 MMAs). ks staggered by warp parity. SCA: scale A fragments by 1/D.
// dskip: skip (mt,nt) sub-tiles entirely above the causal diagonal
// (accumulators stay 0; epilogue masks those outputs to 0 anyway).
// ---------------------------------------------------------------------------
template <bool TRB, bool SCA>
__device__ __forceinline__ void compute_chunk(const __half* As, const __half* Bs,
                                              const __half2* __restrict__ ds,
                                              float c[4][8][4],
                                              int wr, int wc, int lane, int wid,
                                              int dskip) {
    const int arow  = lane & 15;
    const int asel  = (lane >> 4) * 8;
    const int bn    = (lane & 7) + ((lane >> 4) << 3);    // NT path
    const int bsel  = ((lane >> 3) & 1) * 8;
    const int tkrow = (lane & 7) + ((lane >> 3) & 1) * 8; // TR path
    const int tnoff = (lane >> 4) * 8;
    const int ks0   = (wid & 1) << 1;
    const int dq    = lane & 3;
    #pragma unroll
    for (int ksi = 0; ksi < 4; ++ksi) {
        const int ks = (ksi + ks0) & 3;
        const int kh = ks * 16;
        uint32_t a[4][4], b[8][2];
        #pragma unroll
        for (int mt = 0; mt < 4; ++mt) {
            uint32_t ad = smem_u32(As + (wr * 64 + mt * 16 + arow) * SA + kh + asel);
            LDSM_X4(a[mt][0], a[mt][1], a[mt][2], a[mt][3], ad);
        }
        if (SCA) {
            __half2 d0 = __ldg(ds + ks * 8 + dq);
            __half2 d1 = __ldg(ds + ks * 8 + 4 + dq);
            #pragma unroll
            for (int mt = 0; mt < 4; ++mt) {
                a[mt][0] = hmul2_u32(a[mt][0], d0);
                a[mt][1] = hmul2_u32(a[mt][1], d0);
                a[mt][2] = hmul2_u32(a[mt][2], d1);
                a[mt][3] = hmul2_u32(a[mt][3], d1);
            }
        }
        #pragma unroll
        for (int np = 0; np < 4; ++np) {
            uint32_t r0, r1, r2, r3;
            if (!TRB) {
                uint32_t ad = smem_u32(Bs + (wc * 64 + np * 16 + bn) * SA + kh + bsel);
                LDSM_X4(r0, r1, r2, r3, ad);
            } else {
                uint32_t ad = smem_u32(Bs + (kh + tkrow) * SBT
                                          + wc * 64 + np * 16 + tnoff);
                LDSM_X4_T(r0, r1, r2, r3, ad);
            }
            b[np * 2][0] = r0;     b[np * 2][1] = r1;
            b[np * 2 + 1][0] = r2; b[np * 2 + 1][1] = r3;
        }
        #pragma unroll
        for (int mt = 0; mt < 4; ++mt)
            #pragma unroll
            for (int nt = 0; nt < 8; ++nt) {
                if (dskip && (wr * 64 + mt * 16 + 15 < wc * 64 + nt * 8))
                    continue;   // fully above causal diagonal
                mma_f16(c[mt][nt], a[mt], b[nt]);
            }
    }
}

// Double-buffered mainloop: C[128x128] += A[128,K] . op(B), 128 threads
template <bool TRB, bool SCA>
__device__ __forceinline__ void gemm_mainloop(__half* smem,
                                              const __half* __restrict__ A, int lda,
                                              const __half* __restrict__ B, int ldb,
                                              const __half2* __restrict__ ds,
                                              int nc, int tid,
                                              float c[4][8][4],
                                              int wr, int wc, int lane, int wid,
                                              int dskip) {
    __half* As0 = smem;
    __half* Bs0 = smem + AHALVES;
    __half* As1 = smem + STAGEH;
    __half* Bs1 = smem + STAGEH + AHALVES;

    load_tile_k(As0, A, lda, tid);
    if (TRB) load_tile_t(Bs0, B, ldb, tid);
    else     load_tile_k(Bs0, B, ldb, tid);
    CP_COMMIT();

    for (int ch = 0; ch < nc; ++ch) {
        const int buf = ch & 1;
        CP_WAIT0();
        __syncthreads();
        if (ch + 1 < nc) {
            __half* An = buf ? As0 : As1;
            __half* Bn = buf ? Bs0 : Bs1;
            load_tile_k(An, A + (size_t)(ch + 1) * BKH, lda, tid);
            if (TRB) load_tile_t(Bn, B + (size_t)(ch + 1) * BKH * ldb, ldb, tid);
            else     load_tile_k(Bn, B + (size_t)(ch + 1) * BKH, ldb, tid);
            CP_COMMIT();
        }
        compute_chunk<TRB, SCA>(buf ? As1 : As0, (buf ? As1 : As0) + AHALVES,
                                SCA ? ds + ch * 32 : (const __half2*)nullptr,
                                c, wr, wc, lane, wid, dskip);
    }
}

__device__ __forceinline__ void zero_acc(float c[4][8][4]) {
    #pragma unroll
    for (int i = 0; i < 4; ++i)
        #pragma unroll
        for (int j = 0; j < 8; ++j)
            #pragma unroll
            for (int k = 0; k < 4; ++k) c[i][j][k] = 0.0f;
}

// ---------------------------------------------------------------------------
// GEMM kernels: 128 threads = 4 warps (wr 0..1, wc 0..1), warp tile 64x64,
// CTA tile 128x128.
// ---------------------------------------------------------------------------
__global__ __launch_bounds__(128) void proj_mma(const float* __restrict__ bq,
                                                const float* __restrict__ bk,
                                                const float* __restrict__ bv) {
    extern __shared__ __half smem[];
    const int tid = threadIdx.x, lane = tid & 31, wid = tid >> 5;
    const int wr = wid >> 1, wc = wid & 1;
    const int which = blockIdx.x >> 2, colT = blockIdx.x & 3;
    const int rowT = blockIdx.y;

    const __half* A = g_xh + (size_t)rowT * 128 * EE;
    const __half* B = g_Wh + (size_t)which * EE * KK + colT * 128;
    __half* Cmat = (which == 0) ? g_Qh : ((which == 1) ? g_Kh : g_Vh);
    const float* bias = (which == 0) ? bq : ((which == 1) ? bk : bv);

    float c[4][8][4];
    zero_acc(c);
    gemm_mainloop<true, false>(smem, A, EE, B, KK, nullptr, EE / BKH, tid,
                               c, wr, wc, lane, wid, 0);

    __half* Crow = Cmat + (size_t)rowT * 128 * KK;
    const int g = lane >> 2, q = lane & 3;
    #pragma unroll
    for (int mt = 0; mt < 4; ++mt) {
        #pragma unroll
        for (int nt = 0; nt < 8; ++nt) {
            const int row = wr * 64 + mt * 16 + g;
            const int col = colT * 128 + wc * 64 + nt * 8 + q * 2;
            float b0 = __ldg(bias + col), b1 = __ldg(bias + col + 1);
            *(__half2*)&Crow[(size_t)row * KK + col] =
                __floats2half2_rn(c[mt][nt][0] + b0, c[mt][nt][1] + b1);
            *(__half2*)&Crow[(size_t)(row + 8) * KK + col] =
                __floats2half2_rn(c[mt][nt][2] + b0, c[mt][nt][3] + b1);
        }
    }
}

__constant__ int PT[10] = {0, 1, 1, 2, 2, 2, 3, 3, 3, 3};
__constant__ int PS[10] = {0, 0, 1, 0, 1, 2, 0, 1, 2, 3};

// Scores: E = exp(scale * Q K^T), causal-zeroed, fp16 into g_S.
// Fused column-sum: per-thread partials atomically added into g_D.
__global__ __launch_bounds__(128) void qkt_mma() {
    extern __shared__ __half smem[];
    const int tid = threadIdx.x, lane = tid & 31, wid = tid >> 5;
    const int wr = wid >> 1, wc = wid & 1;
    const int tT = PT[blockIdx.x], sT = PS[blockIdx.x], b = blockIdx.y;
    const int dskip = (tT == sT) ? 1 : 0;

    const __half* A = g_Qh + (size_t)b * TT * KK + (size_t)tT * 128 * KK;
    const __half* B = g_Kh + (size_t)b * TT * KK + (size_t)sT * 128 * KK;

    float c[4][8][4];
    zero_acc(c);
    gemm_mainloop<false, false>(smem, A, KK, B, KK, nullptr, KK / BKH, tid,
                                c, wr, wc, lane, wid, dskip);

    const float SCALE = 0.04419417382415922f;   // 1/sqrt(512)
    __half* Crow = g_S + (size_t)b * TT * TT + (size_t)tT * 128 * TT;
    float* Dall = g_D + (size_t)b * TT;
    const int g = lane >> 2, q = lane & 3;
    #pragma unroll
    for (int nt = 0; nt < 8; ++nt) {
        float cs0 = 0.0f, cs1 = 0.0f;
        #pragma unroll
        for (int mt = 0; mt < 4; ++mt) {
            const int row = wr * 64 + mt * 16 + g;
            const int col = wc * 64 + nt * 8 + q * 2;
            const int tg0 = tT * 128 + row, tg1 = tg0 + 8;
            const int sg0 = sT * 128 + col, sg1 = sg0 + 1;
            float e00 = (tg0 >= sg0) ? __expf(c[mt][nt][0] * SCALE) : 0.0f;
            float e01 = (tg0 >= sg1) ? __expf(c[mt][nt][1] * SCALE) : 0.0f;
            float e10 = (tg1 >= sg0) ? __expf(c[mt][nt][2] * SCALE) : 0.0f;
            float e11 = (tg1 >= sg1) ? __expf(c[mt][nt][3] * SCALE) : 0.0f;
            *(__half2*)&Crow[(size_t)row * TT + sT * 128 + col] =
                __floats2half2_rn(e00, e01);
            *(__half2*)&Crow[(size_t)(row + 8) * TT + sT * 128 + col] =
                __floats2half2_rn(e10, e11);
            cs0 += e00 + e10;
            cs1 += e01 + e11;
        }
        const int colg = sT * 128 + wc * 64 + nt * 8 + q * 2;
        atomicAdd(Dall + colg, cs0);
        atomicAdd(Dall + colg + 1, cs1);
    }
}

// 1/D: fp32 accumulators -> fp16 reciprocals
__global__ __launch_bounds__(256) void recip_kernel() {
    const int i = blockIdx.x * 256 + threadIdx.x;
    g_Dr[i] = __float2half(1.0f / g_D[i]);
}

// Output: out = (E . diag(1/D)) @ V, causal K cutoff, A-frags scaled in regs
__global__ __launch_bounds__(128) void av_mma(float* __restrict__ out) {
    extern __shared__ __half smem[];
    const int tid = threadIdx.x, lane = tid & 31, wid = tid >> 5;
    const int wr = wid >> 1, wc = wid & 1;
    const int vT = blockIdx.x, tT = 3 - blockIdx.y, b = blockIdx.z;  // heavy first

    const __half* A = g_S  + (size_t)b * TT * TT + (size_t)tT * 128 * TT;
    const __half* B = g_Vh + (size_t)b * TT * VV + vT * 128;
    const __half2* ds = (const __half2*)(g_Dr + (size_t)b * TT);
    const int nc = (tT + 1) * (128 / BKH);     // causal K cutoff

    float c[4][8][4];
    zero_acc(c);
    gemm_mainloop<true, true>(smem, A, TT, B, VV, ds, nc, tid,
                              c, wr, wc, lane, wid, 0);

    float* Crow = out + (size_t)b * TT * VV + (size_t)tT * 128 * VV;
    const int g = lane >> 2, q = lane & 3;
    #pragma unroll
    for (int mt = 0; mt < 4; ++mt) {
        #pragma unroll
        for (int nt = 0; nt < 8; ++nt) {
            const int row = wr * 64 + mt * 16 + g;
            const int col = vT * 128 + wc * 64 + nt * 8 + q * 2;
            *(float2*)&Crow[(size_t)row * VV + col] =
                make_float2(c[mt][nt][0], c[mt][nt][1]);
            *(float2*)&Crow[(size_t)(row + 8) * VV + col] =
                make_float2(c[mt][nt][2], c[mt][nt][3]);
        }
    }
}

// ---------------------------------------------------------------------------
// Aux kernels
// ---------------------------------------------------------------------------
__global__ __launch_bounds__(256) void convx_kernel(const float* __restrict__ x) {
    size_t i = ((size_t)blockIdx.x * 256 + threadIdx.x) * 4;
    float4 v = *(const float4*)(x + i);
    __half2* d = (__half2*)(g_xh + i);
    d[0] = __floats2half2_rn(v.x, v.y);
    d[1] = __floats2half2_rn(v.z, v.w);
}

// Converts W to fp16; also zeroes the colsum accumulators g_D.
__global__ __launch_bounds__(256) void convw_kernel(const float* __restrict__ Wq,
                                                    const float* __restrict__ Wk,
                                                    const float* __restrict__ Wv) {
    const int which = blockIdx.y;
    const float* W = (which == 0) ? Wq : ((which == 1) ? Wk : Wv);
    __half* D = g_Wh + (size_t)which * EE * KK;
    size_t i = ((size_t)blockIdx.x * 256 + threadIdx.x) * 4;
    float4 v = *(const float4*)(W + i);
    __half2* d = (__half2*)(D + i);
    d[0] = __floats2half2_rn(v.x, v.y);
    d[1] = __floats2half2_rn(v.z, v.w);
    if (which == 0 && blockIdx.x < 32) {
        size_t zi = ((size_t)blockIdx.x * 256 + threadIdx.x) * 4;  // < 32768
        *(float4*)(g_D + zi) = make_float4(0.f, 0.f, 0.f, 0.f);
    }
}

// ---------------------------------------------------------------------------
extern "C" void kernel_launch(void* const* d_in, const int* in_sizes, int n_in,
                              void* d_out, int out_size) {
    const float* x  = (const float*)d_in[0];
    const float* Wq = (const float*)d_in[1];
    const float* bq = (const float*)d_in[2];
    const float* Wk = (const float*)d_in[3];
    const float* bk = (const float*)d_in[4];
    const float* Wv = (const float*)d_in[5];
    const float* bv = (const float*)d_in[6];
    float* out = (float*)d_out;

    cudaFuncSetAttribute(proj_mma, cudaFuncAttributeMaxDynamicSharedMemorySize, SMEM_BYTES);
    cudaFuncSetAttribute(qkt_mma,  cudaFuncAttributeMaxDynamicSharedMemorySize, SMEM_BYTES);
    cudaFuncSetAttribute(av_mma,   cudaFuncAttributeMaxDynamicSharedMemorySize, SMEM_BYTES);

    convx_kernel<<<(NB * TT * EE) / (256 * 4), 256>>>(x);
    convw_kernel<<<dim3((EE * KK) / (256 * 4), 3), 256>>>(Wq, Wk, Wv);
    proj_mma    <<<dim3(12, 256), 128, SMEM_BYTES>>>(bq, bk, bv);
    qkt_mma     <<<dim3(10, 64), 128, SMEM_BYTES>>>();
    recip_kernel<<<(NB * TT) / 256, 256>>>();
    av_mma      <<<dim3(4, 4, 64), 128, SMEM_BYTES>>>(out);
}